// round 9
// baseline (speedup 1.0000x reference)
#include <cuda_runtime.h>
#include <math.h>

// Problem constants
#define CIN    128
#define CMID   16
#define COUT   256
#define HW     12544
#define WIDTH  112
#define NBLK   784
#define NTHR   512

// Pooling segments 16 -> 7 (overlapping avg pool)
__constant__ int   SEG_S[7] = {0, 2, 4, 6, 9, 11, 13};
__constant__ int   SEG_E[7] = {3, 5, 7, 10, 12, 14, 16};
__constant__ float SEG_I[7] = {1.f/3.f, 1.f/3.f, 1.f/3.f, 0.25f, 1.f/3.f, 1.f/3.f, 1.f/3.f};

// ---- packed f32x2 helpers (sm_103a, PTX-only) ----
__device__ __forceinline__ unsigned long long pk2(float a, float b) {
    unsigned long long r;
    asm("mov.b64 %0, {%1, %2};" : "=l"(r) : "f"(a), "f"(b));
    return r;
}
__device__ __forceinline__ unsigned long long ffma2(unsigned long long a,
                                                    unsigned long long b,
                                                    unsigned long long c) {
    unsigned long long d;
    asm("fma.rn.f32x2 %0, %1, %2, %3;" : "=l"(d) : "l"(a), "l"(b), "l"(c));
    return d;
}
__device__ __forceinline__ unsigned long long fmul2(unsigned long long a,
                                                    unsigned long long b) {
    unsigned long long d;
    asm("mul.rn.f32x2 %0, %1, %2;" : "=l"(d) : "l"(a), "l"(b));
    return d;
}
__device__ __forceinline__ unsigned long long fadd2(unsigned long long a,
                                                    unsigned long long b) {
    unsigned long long d;
    asm("add.rn.f32x2 %0, %1, %2;" : "=l"(d) : "l"(a), "l"(b));
    return d;
}
__device__ __forceinline__ float2 upk(unsigned long long v) {
    float2 f;
    asm("mov.b64 {%0, %1}, %2;" : "=f"(f.x), "=f"(f.y) : "l"(v));
    return f;
}

#define SGNMASK 0x8000000080000000ULL
#define OFFSET_F 16384.0f

// Exact compensated accumulate (fallback path only).
__device__ __forceinline__ void dfacc2(unsigned long long& hi, unsigned long long& lo,
                                       unsigned long long xd, unsigned long long w) {
    unsigned long long ph = fmul2(xd, w);
    unsigned long long pl = ffma2(xd, w, ph ^ SGNMASK);
    unsigned long long s  = fadd2(hi, ph);
    unsigned long long d  = fadd2(hi, s ^ SGNMASK);
    unsigned long long e  = fadd2(d, ph);
    lo = fadd2(lo, fadd2(e, pl));
    hi = s;
}

// Shared memory byte-offsets
#define FSTR 257     // stride (floats for fs/vs, doubles for fsd)
#define MSTR 18      // midT stride (floats), conflict-dodged
#define OFF_R0    0                          // union: fs float[16*257] (common)
                                             //        fsd double[16*257] (fallback)
                                             //        midT float[256*18] (stage D)
#define OFF_CFD   (OFF_R0 + 16*FSTR*8)       // double[784] exact centers (fallback)
#define OFF_WBUF  (OFF_CFD + 784*8)          // float[4096] time-shared:
                                             //  A: wsf[0:2048] wsv[2048:4096]
                                             //  B/C: vc[0:784] cf32[784:1568]
                                             //  fallback: fw2[1568:3616]
                                             //  D: pwt2[0:4096] (pw as-is, [o][cc])
#define OFF_VS    (OFF_WBUF + 4096*4)        // float[16*257] v features
#define OFF_AGN   (OFF_VS  + 16*FSTR*4)      // float[784]
#define OFF_AGD   (OFF_AGN + 784*4)          // float[52]
#define OFF_FBS   (OFF_AGD + 52*4)           // float[16]
#define OFF_VBS   (OFF_FBS + 16*4)           // float[16]
#define OFF_PBS   (OFF_VBS + 16*4)           // float[256]
#define SMEM_BYTES (OFF_PBS + 256*4)         // 76,496 B -> 3 CTAs/SM @512thr

extern "C" __global__ void __launch_bounds__(NTHR, 3)
lc_kernel(const float* __restrict__ x,   const float* __restrict__ fw,
          const float* __restrict__ fb,  const float* __restrict__ vw,
          const float* __restrict__ vb,  const float* __restrict__ pw,
          const float* __restrict__ pbg, const float* __restrict__ salpha,
          const float* __restrict__ sbeta, float* __restrict__ out)
{
    extern __shared__ char smraw[];
    float*  fs   = (float*)(smraw + OFF_R0);
    double* fsd  = (double*)(smraw + OFF_R0);
    float*  midT = (float*)(smraw + OFF_R0);
    double* cfd  = (double*)(smraw + OFF_CFD);
    float*  wbuf = (float*)(smraw + OFF_WBUF);
    float*  vs   = (float*)(smraw + OFF_VS);
    float*  agn  = (float*)(smraw + OFF_AGN);
    float*  agd  = (float*)(smraw + OFF_AGD);
    float*  fbs  = (float*)(smraw + OFF_FBS);
    float*  vbs  = (float*)(smraw + OFF_VBS);
    float*  pbs  = (float*)(smraw + OFF_PBS);
    float*  wsf  = wbuf;
    float*  wsv  = wbuf + 2048;
    float*  vc   = wbuf;
    float*  cf32 = wbuf + 784;
    float*  fw2  = wbuf + 1568;
    float*  pwt2 = wbuf;

    const int t = threadIdx.x;
    const int b = blockIdx.x;
    const int batch = b / 49;
    const int g = b - batch * 49;
    const int gx = g / 7, gy = g - (g / 7) * 7;

    // ---- stage A weights + biases into smem ----
    for (int i = t; i < 2048; i += NTHR) {
        int c = i >> 4, o = i & 15;
        wsf[i] = fw[o * CIN + c];
        wsv[i] = vw[o * CIN + c];
    }
    if (t < 16) { fbs[t] = fb[t]; vbs[t] = vb[t]; }
    if (t < 256) pbs[t] = pbg[t];
    for (int i = t; i < 784; i += NTHR) agn[i] = 0.f;
    if (t < 49) agd[t] = 0.f;
    __syncthreads();

    // ---- Stage A: warps 0-7 -> f, warps 8-15 -> v (1 pixel, 128 ch each) ----
    const int px  = t & 255;             // pixel
    const int prj = t >> 8;              // 0 = f, 1 = v
    const int apr = px >> 4, apc = px & 15;
    const float* xa = x + (size_t)batch * COUT * HW + (size_t)prj * CIN * HW
                        + (size_t)(gx * 16 + apr) * WIDTH + (gy * 16 + apc);
    const float* wsel = prj ? wsv : wsf;
    {
        unsigned long long acc[8];
        #pragma unroll
        for (int j = 0; j < 8; j++) acc[j] = 0ull;
        #pragma unroll 4
        for (int c = 0; c < CIN; c++) {
            float xv = __ldg(xa + (size_t)c * HW);
            unsigned long long xd = pk2(xv, xv);
            const ulonglong2* wr = (const ulonglong2*)(wsel + c * 16);
            #pragma unroll
            for (int j = 0; j < 4; j++) {
                ulonglong2 a = wr[j];
                acc[2*j]   = ffma2(xd, a.x, acc[2*j]);
                acc[2*j+1] = ffma2(xd, a.y, acc[2*j+1]);
            }
        }
        float* dst = prj ? vs : fs;
        const float* bsel = prj ? vbs : fbs;
        #pragma unroll
        for (int j = 0; j < 8; j++) {
            float2 v = upk(acc[j]);
            dst[(2*j)   * FSTR + px] = v.x + bsel[2*j];
            dst[(2*j+1) * FSTR + px] = v.y + bsel[2*j+1];
        }
    }
    __syncthreads();

    // ---- Stage B: fp32 pooling (centers cf32, value centers vc) ----
    for (int it = t; it < 1568; it += NTHR) {
        int half = it >= 784;
        int rem = half ? it - 784 : it;
        int m = rem >> 4, cc = rem & 15;
        int i = m / 7, jj = m - i * 7;
        const float* src = half ? vs : fs;
        float ssum = 0.f;
        for (int r = SEG_S[i]; r < SEG_E[i]; r++)
            for (int q = SEG_S[jj]; q < SEG_E[jj]; q++)
                ssum += src[cc * FSTR + r * 16 + q];
        ssum *= SEG_I[i] * SEG_I[jj];
        if (half) vc[rem] = ssum; else cf32[rem] = ssum;
    }
    __syncthreads();

    if (t < 49) {
        float ss = 0.f;
        #pragma unroll
        for (int cc = 0; cc < 16; cc++) {
            float v = cf32[t*16+cc];
            ss = __fmaf_rn(v, v, ss);
        }
        float inv = 1.f / fmaxf(sqrtf(ss), 1e-12f);
        #pragma unroll
        for (int cc = 0; cc < 16; cc++) cf32[t*16+cc] *= inv;
    }
    __syncthreads();

    // ---- Stage C (common, lower 256 threads): fp32 dots, top-2, gap test ----
    float ffn[16];
    float z1 = 1e30f, z2 = 0.f;          // upper threads: gap huge -> no vote
    int bm = 0;
    float s = 0.f;
    const float alphaf = __ldg(salpha);
    const float betaf  = __ldg(sbeta);
    if (t < 256) {
        float ss = 0.f;
        #pragma unroll
        for (int cc = 0; cc < 16; cc++) {
            float v = fs[cc * FSTR + t];
            ffn[cc] = v;
            ss = __fmaf_rn(v, v, ss);
        }
        float inv = 1.f / fmaxf(sqrtf(ss), 1e-12f);
        #pragma unroll
        for (int cc = 0; cc < 16; cc++) ffn[cc] *= inv;

        z1 = -1e30f; z2 = -1e30f;
        for (int m = 0; m < 49; m++) {
            const float4* cr = (const float4*)(cf32 + m * 16);
            float dot = 0.f;
            #pragma unroll
            for (int q = 0; q < 4; q++) {
                float4 w = cr[q];
                dot = __fmaf_rn(w.x, ffn[4*q+0], dot);
                dot = __fmaf_rn(w.y, ffn[4*q+1], dot);
                dot = __fmaf_rn(w.z, ffn[4*q+2], dot);
                dot = __fmaf_rn(w.w, ffn[4*q+3], dot);
            }
            float z = betaf + alphaf * dot;
            if (z > z1) { z2 = z1; z1 = z; bm = m; }
            else if (z > z2) { z2 = z; }
        }
        s = 1.f / (1.f + expf(-z1));
    }

    // ---- per-CTA vote: exact fallback if any pixel too close to call ----
    if (__syncthreads_or((z1 - z2) < 1e-4f)) {
        for (int i = t; i < 2048; i += NTHR) {
            int c = i >> 4, o = i & 15;
            fw2[i] = fw[o * CIN + c];
        }
        __syncthreads();

        unsigned long long fhi[8], flo[8];
        if (t < 256) {
            #pragma unroll
            for (int j = 0; j < 8; j++) { fhi[j] = pk2(OFFSET_F, OFFSET_F); flo[j] = 0ull; }
            const float* xf = x + (size_t)batch * COUT * HW
                                + (size_t)(gx * 16 + apr) * WIDTH + (gy * 16 + apc);
            #pragma unroll 2
            for (int c = 0; c < CIN; c++) {
                float x1 = __ldg(xf + (size_t)c * HW);
                unsigned long long x1d = pk2(x1, x1);
                const ulonglong2* wf = (const ulonglong2*)(fw2 + c * 16);
                #pragma unroll
                for (int j = 0; j < 4; j++) {
                    ulonglong2 a = wf[j];
                    dfacc2(fhi[2*j],   flo[2*j],   x1d, a.x);
                    dfacc2(fhi[2*j+1], flo[2*j+1], x1d, a.y);
                }
            }
        }
        __syncthreads();     // all fs readers done before fp64 overwrite
        if (t < 256) {
            #pragma unroll
            for (int j = 0; j < 8; j++) {
                float2 h = upk(fhi[j]), l = upk(flo[j]);
                fsd[(2*j)   * FSTR + t] =
                    ((double)__fadd_rn(h.x, -OFFSET_F) + (double)l.x) + (double)fbs[2*j];
                fsd[(2*j+1) * FSTR + t] =
                    ((double)__fadd_rn(h.y, -OFFSET_F) + (double)l.y) + (double)fbs[2*j+1];
            }
        }
        __syncthreads();

        for (int it = t; it < 784; it += NTHR) {
            int m = it >> 4, cc = it & 15;
            int i = m / 7, jj = m - i * 7;
            double ssum = 0.0;
            for (int r = SEG_S[i]; r < SEG_E[i]; r++)
                for (int q = SEG_S[jj]; q < SEG_E[jj]; q++)
                    ssum += fsd[cc * FSTR + r * 16 + q];
            cfd[it] = ssum * (double)SEG_I[i] * (double)SEG_I[jj];
        }
        __syncthreads();
        if (t < 49) {
            double ss = 0.0;
            #pragma unroll
            for (int cc = 0; cc < 16; cc++) { double v = cfd[t*16+cc]; ss = fma(v, v, ss); }
            double inv = 1.0 / fmax(sqrt(ss), 1e-12);
            #pragma unroll
            for (int cc = 0; cc < 16; cc++) cfd[t*16+cc] *= inv;
        }
        __syncthreads();

        if (t < 256) {
            double invf;
            {
                double ss = 0.0;
                #pragma unroll
                for (int cc = 0; cc < 16; cc++) {
                    double v = fsd[cc * FSTR + t];
                    ss = fma(v, v, ss);
                }
                invf = 1.0 / fmax(sqrt(ss), 1e-12);
            }
            const double alpha = (double)alphaf;
            const double beta  = (double)betaf;

            float mx32 = -1e30f;
            for (int m = 0; m < 49; m++) {
                const float4* cr = (const float4*)(cf32 + m * 16);
                float dot = 0.f;
                #pragma unroll
                for (int q = 0; q < 4; q++) {
                    float4 w = cr[q];
                    dot = __fmaf_rn(w.x, ffn[4*q+0], dot);
                    dot = __fmaf_rn(w.y, ffn[4*q+1], dot);
                    dot = __fmaf_rn(w.z, ffn[4*q+2], dot);
                    dot = __fmaf_rn(w.w, ffn[4*q+3], dot);
                }
                mx32 = fmaxf(mx32, dot);
            }
            const float thr = mx32 - 1e-4f;
            double dz1 = -1e300, dz2 = -1e300, dz3 = -1e300;
            int m1 = 0, m2 = 0, m3 = 0;
            for (int m = 0; m < 49; m++) {
                const float4* cr = (const float4*)(cf32 + m * 16);
                float dot = 0.f;
                #pragma unroll
                for (int q = 0; q < 4; q++) {
                    float4 w = cr[q];
                    dot = __fmaf_rn(w.x, ffn[4*q+0], dot);
                    dot = __fmaf_rn(w.y, ffn[4*q+1], dot);
                    dot = __fmaf_rn(w.z, ffn[4*q+2], dot);
                    dot = __fmaf_rn(w.w, ffn[4*q+3], dot);
                }
                if (dot >= thr) {
                    double dd = 0.0;
                    #pragma unroll
                    for (int cc = 0; cc < 16; cc++)
                        dd = fma(cfd[m*16+cc], fsd[cc * FSTR + t], dd);
                    double z = beta + alpha * (dd * invf);
                    if (z > dz1)      { dz3 = dz2; m3 = m2; dz2 = dz1; m2 = m1; dz1 = z; m1 = m; }
                    else if (z > dz2) { dz3 = dz2; m3 = m2; dz2 = z;  m2 = m; }
                    else if (z > dz3) { dz3 = z;  m3 = m; }
                }
            }
            float s1f = (float)(1.0 / (1.0 + exp(-dz1)));
            bm = m1;
            if (dz1 - dz2 < 1e-5) {
                float s2f = (float)(1.0 / (1.0 + exp(-dz2)));
                if (s2f == s1f && m2 < bm) bm = m2;
                if (dz1 - dz3 < 1e-5) {
                    float s3f = (float)(1.0 / (1.0 + exp(-dz3)));
                    if (s3f == s1f && m3 < bm) bm = m3;
                }
            }
            s = s1f;
        }
        __syncthreads();
    }

    // ---- aggregate (lower 256 threads) ----
    if (t < 256) {
        atomicAdd(&agd[bm], s);
        #pragma unroll
        for (int cc = 0; cc < 16; cc++)
            atomicAdd(&agn[bm * 16 + cc], s * vs[cc * FSTR + t]);
    }
    __syncthreads();

    for (int it = t; it < 784; it += NTHR) {
        int m = it >> 4;
        agn[it] = (agn[it] + vc[it]) / (agd[m] + 1.f);
    }
    __syncthreads();

    // ---- write midT[n][cc] (transposed; fs region is dead now) ----
    if (t < 256) {
        #pragma unroll
        for (int q = 0; q < 8; q++) {
            float a = s * agn[bm * 16 + 2*q];
            float c = s * agn[bm * 16 + 2*q + 1];
            *(unsigned long long*)(midT + t * MSTR + 2*q) = pk2(a, c);
        }
    }
    // ---- load p weights as-is ([o][cc], row-major) ----
    for (int i = t; i < 1024; i += NTHR)
        ((float4*)pwt2)[i] = ((const float4*)pw)[i];
    __syncthreads();

    // ---- Stage D: thread = (o-group of 64) x (pixel pair), pixels sequential ----
    {
        const int nid = t & 127, oid = t >> 7;
        const int obase = oid << 6;
        float* ybase = out + (size_t)batch * COUT * HW;
        #pragma unroll
        for (int p = 0; p < 2; p++) {
            const int n = 2 * nid + p;
            unsigned long long mid[8];
            #pragma unroll
            for (int q = 0; q < 8; q++)
                mid[q] = *(const unsigned long long*)(midT + n * MSTR + 2*q);
            float* yb = ybase + (size_t)(gx * 16 + (n >> 4)) * WIDTH
                              + (gy * 16 + (n & 15));
            #pragma unroll 4
            for (int i = 0; i < 64; i++) {
                const int o = obase + i;
                const ulonglong2* wr = (const ulonglong2*)(pwt2 + o * 16);
                unsigned long long a = 0ull;
                ulonglong2 w0 = wr[0];
                a = ffma2(w0.x, mid[0], a);
                a = ffma2(w0.y, mid[1], a);
                ulonglong2 w1 = wr[1];
                a = ffma2(w1.x, mid[2], a);
                a = ffma2(w1.y, mid[3], a);
                ulonglong2 w2 = wr[2];
                a = ffma2(w2.x, mid[4], a);
                a = ffma2(w2.y, mid[5], a);
                ulonglong2 w3 = wr[3];
                a = ffma2(w3.x, mid[6], a);
                a = ffma2(w3.y, mid[7], a);
                float2 f = upk(a);
                yb[(size_t)o * HW] = pbs[o] + f.x + f.y;
            }
        }
    }
}

extern "C" void kernel_launch(void* const* d_in, const int* in_sizes, int n_in,
                              void* d_out, int out_size) {
    const float* x   = (const float*)d_in[0];
    const float* fw  = (const float*)d_in[1];
    const float* fb  = (const float*)d_in[2];
    const float* vw  = (const float*)d_in[3];
    const float* vb  = (const float*)d_in[4];
    const float* pw  = (const float*)d_in[5];
    const float* pb  = (const float*)d_in[6];
    const float* sa  = (const float*)d_in[7];
    const float* sb  = (const float*)d_in[8];
    float* out = (float*)d_out;

    cudaFuncSetAttribute(lc_kernel, cudaFuncAttributeMaxDynamicSharedMemorySize,
                         SMEM_BYTES);
    lc_kernel<<<NBLK, NTHR, SMEM_BYTES>>>(x, fw, fb, vw, vb, pw, pb, sa, sb, out);
}

// round 10
// speedup vs baseline: 1.3185x; 1.3185x over previous
#include <cuda_runtime.h>
#include <math.h>

// Problem constants
#define CIN    128
#define CMID   16
#define COUT   256
#define HW     12544
#define WIDTH  112
#define NBLK   784
#define NTHR   512

// Pooling segments 16 -> 7 (overlapping avg pool)
__constant__ int   SEG_S[7] = {0, 2, 4, 6, 9, 11, 13};
__constant__ int   SEG_E[7] = {3, 5, 7, 10, 12, 14, 16};
__constant__ float SEG_I[7] = {1.f/3.f, 1.f/3.f, 1.f/3.f, 0.25f, 1.f/3.f, 1.f/3.f, 1.f/3.f};

// ---- packed f32x2 helpers (sm_103a, PTX-only) ----
__device__ __forceinline__ unsigned long long pk2(float a, float b) {
    unsigned long long r;
    asm("mov.b64 %0, {%1, %2};" : "=l"(r) : "f"(a), "f"(b));
    return r;
}
__device__ __forceinline__ unsigned long long ffma2(unsigned long long a,
                                                    unsigned long long b,
                                                    unsigned long long c) {
    unsigned long long d;
    asm("fma.rn.f32x2 %0, %1, %2, %3;" : "=l"(d) : "l"(a), "l"(b), "l"(c));
    return d;
}
__device__ __forceinline__ unsigned long long fmul2(unsigned long long a,
                                                    unsigned long long b) {
    unsigned long long d;
    asm("mul.rn.f32x2 %0, %1, %2;" : "=l"(d) : "l"(a), "l"(b));
    return d;
}
__device__ __forceinline__ unsigned long long fadd2(unsigned long long a,
                                                    unsigned long long b) {
    unsigned long long d;
    asm("add.rn.f32x2 %0, %1, %2;" : "=l"(d) : "l"(a), "l"(b));
    return d;
}
__device__ __forceinline__ float2 upk(unsigned long long v) {
    float2 f;
    asm("mov.b64 {%0, %1}, %2;" : "=f"(f.x), "=f"(f.y) : "l"(v));
    return f;
}

#define SGNMASK 0x8000000080000000ULL
#define OFFSET_F 16384.0f

// Exact compensated accumulate (fallback path only).
__device__ __forceinline__ void dfacc2(unsigned long long& hi, unsigned long long& lo,
                                       unsigned long long xd, unsigned long long w) {
    unsigned long long ph = fmul2(xd, w);
    unsigned long long pl = ffma2(xd, w, ph ^ SGNMASK);
    unsigned long long s  = fadd2(hi, ph);
    unsigned long long d  = fadd2(hi, s ^ SGNMASK);
    unsigned long long e  = fadd2(d, ph);
    lo = fadd2(lo, fadd2(e, pl));
    hi = s;
}

// Shared memory byte-offsets
#define FSTR 257     // stride (floats for fs/vs, doubles for fsd)
#define PSTR 129     // P tile stride (floats), bank-spread for [m][o] gather
#define OFF_R0    0                          // union: fs float[16*257] (common)
                                             //        fsd double[16*257] (fallback)
                                             //        P float[49*129] + sp/bmi (D)
#define OFF_SP    (OFF_R0 + 6336*4)          // float[256] pixel sigmoid s
#define OFF_BMI   (OFF_SP + 256*4)           // int[256]   pixel best cluster
#define OFF_CFD   (OFF_R0 + 16*FSTR*8)       // double[784] exact centers (fallback)
#define OFF_WBUF  (OFF_CFD + 784*8)          // float[4096] time-shared:
                                             //  A: wsf[0:2048] wsv[2048:4096]
                                             //  B/C: vc[0:784] cf32[784:1568]
                                             //  fallback: fw2[1568:3616]
                                             //  D: pws[0:4096] (pw as-is [o][cc])
#define OFF_VS    (OFF_WBUF + 4096*4)        // float[16*257] v features
#define OFF_AGN   (OFF_VS  + 16*FSTR*4)      // float[784]
#define OFF_AGD   (OFF_AGN + 784*4)          // float[52]
#define OFF_FBS   (OFF_AGD + 52*4)           // float[16]
#define OFF_VBS   (OFF_FBS + 16*4)           // float[16]
#define OFF_PBS   (OFF_VBS + 16*4)           // float[256]
#define SMEM_BYTES (OFF_PBS + 256*4)         // 76,496 B -> 2 CTAs/SM @512thr

extern "C" __global__ void __launch_bounds__(NTHR, 2)
lc_kernel(const float* __restrict__ x,   const float* __restrict__ fw,
          const float* __restrict__ fb,  const float* __restrict__ vw,
          const float* __restrict__ vb,  const float* __restrict__ pw,
          const float* __restrict__ pbg, const float* __restrict__ salpha,
          const float* __restrict__ sbeta, float* __restrict__ out)
{
    extern __shared__ char smraw[];
    float*  fs   = (float*)(smraw + OFF_R0);
    double* fsd  = (double*)(smraw + OFF_R0);
    float*  Pm   = (float*)(smraw + OFF_R0);      // stage D P tile [49][129]
    float*  sp   = (float*)(smraw + OFF_SP);
    int*    bmi  = (int*)(smraw + OFF_BMI);
    double* cfd  = (double*)(smraw + OFF_CFD);
    float*  wbuf = (float*)(smraw + OFF_WBUF);
    float*  vs   = (float*)(smraw + OFF_VS);
    float*  agn  = (float*)(smraw + OFF_AGN);
    float*  agd  = (float*)(smraw + OFF_AGD);
    float*  fbs  = (float*)(smraw + OFF_FBS);
    float*  vbs  = (float*)(smraw + OFF_VBS);
    float*  pbs  = (float*)(smraw + OFF_PBS);
    float*  wsf  = wbuf;
    float*  wsv  = wbuf + 2048;
    float*  vc   = wbuf;
    float*  cf32 = wbuf + 784;
    float*  fw2  = wbuf + 1568;
    float*  pws  = wbuf;

    const int t = threadIdx.x;
    const int b = blockIdx.x;
    const int batch = b / 49;
    const int g = b - batch * 49;
    const int gx = g / 7, gy = g - (g / 7) * 7;

    // ---- stage A weights + biases into smem ----
    for (int i = t; i < 2048; i += NTHR) {
        int c = i >> 4, o = i & 15;
        wsf[i] = fw[o * CIN + c];
        wsv[i] = vw[o * CIN + c];
    }
    if (t < 16) { fbs[t] = fb[t]; vbs[t] = vb[t]; }
    if (t < 256) pbs[t] = pbg[t];
    for (int i = t; i < 784; i += NTHR) agn[i] = 0.f;
    if (t < 49) agd[t] = 0.f;
    __syncthreads();

    // ---- Stage A: warps 0-7 -> f, warps 8-15 -> v (1 pixel, 128 ch each) ----
    const int px  = t & 255;             // pixel
    const int prj = t >> 8;              // 0 = f, 1 = v
    const int apr = px >> 4, apc = px & 15;
    const float* xa = x + (size_t)batch * COUT * HW + (size_t)prj * CIN * HW
                        + (size_t)(gx * 16 + apr) * WIDTH + (gy * 16 + apc);
    const float* wsel = prj ? wsv : wsf;
    {
        unsigned long long acc[8];
        #pragma unroll
        for (int j = 0; j < 8; j++) acc[j] = 0ull;
        #pragma unroll 8
        for (int c = 0; c < CIN; c++) {
            float xv = __ldg(xa + (size_t)c * HW);
            unsigned long long xd = pk2(xv, xv);
            const ulonglong2* wr = (const ulonglong2*)(wsel + c * 16);
            #pragma unroll
            for (int j = 0; j < 4; j++) {
                ulonglong2 a = wr[j];
                acc[2*j]   = ffma2(xd, a.x, acc[2*j]);
                acc[2*j+1] = ffma2(xd, a.y, acc[2*j+1]);
            }
        }
        float* dst = prj ? vs : fs;
        const float* bsel = prj ? vbs : fbs;
        #pragma unroll
        for (int j = 0; j < 8; j++) {
            float2 v = upk(acc[j]);
            dst[(2*j)   * FSTR + px] = v.x + bsel[2*j];
            dst[(2*j+1) * FSTR + px] = v.y + bsel[2*j+1];
        }
    }
    __syncthreads();

    // ---- Stage B: fp32 pooling (centers cf32, value centers vc) ----
    for (int it = t; it < 1568; it += NTHR) {
        int half = it >= 784;
        int rem = half ? it - 784 : it;
        int m = rem >> 4, cc = rem & 15;
        int i = m / 7, jj = m - i * 7;
        const float* src = half ? vs : fs;
        float ssum = 0.f;
        for (int r = SEG_S[i]; r < SEG_E[i]; r++)
            for (int q = SEG_S[jj]; q < SEG_E[jj]; q++)
                ssum += src[cc * FSTR + r * 16 + q];
        ssum *= SEG_I[i] * SEG_I[jj];
        if (half) vc[rem] = ssum; else cf32[rem] = ssum;
    }
    __syncthreads();

    if (t < 49) {
        float ss = 0.f;
        #pragma unroll
        for (int cc = 0; cc < 16; cc++) {
            float v = cf32[t*16+cc];
            ss = __fmaf_rn(v, v, ss);
        }
        float inv = 1.f / fmaxf(sqrtf(ss), 1e-12f);
        #pragma unroll
        for (int cc = 0; cc < 16; cc++) cf32[t*16+cc] *= inv;
    }
    __syncthreads();

    // ---- Stage C (common, lower 256 threads): fp32 dots, top-2, gap test ----
    float ffn[16];
    float z1 = 1e30f, z2 = 0.f;          // upper threads: gap huge -> no vote
    int bm = 0;
    float s = 0.f;
    const float alphaf = __ldg(salpha);
    const float betaf  = __ldg(sbeta);
    if (t < 256) {
        float ss = 0.f;
        #pragma unroll
        for (int cc = 0; cc < 16; cc++) {
            float v = fs[cc * FSTR + t];
            ffn[cc] = v;
            ss = __fmaf_rn(v, v, ss);
        }
        float inv = 1.f / fmaxf(sqrtf(ss), 1e-12f);
        #pragma unroll
        for (int cc = 0; cc < 16; cc++) ffn[cc] *= inv;

        z1 = -1e30f; z2 = -1e30f;
        for (int m = 0; m < 49; m++) {
            const float4* cr = (const float4*)(cf32 + m * 16);
            float dot = 0.f;
            #pragma unroll
            for (int q = 0; q < 4; q++) {
                float4 w = cr[q];
                dot = __fmaf_rn(w.x, ffn[4*q+0], dot);
                dot = __fmaf_rn(w.y, ffn[4*q+1], dot);
                dot = __fmaf_rn(w.z, ffn[4*q+2], dot);
                dot = __fmaf_rn(w.w, ffn[4*q+3], dot);
            }
            float z = betaf + alphaf * dot;
            if (z > z1) { z2 = z1; z1 = z; bm = m; }
            else if (z > z2) { z2 = z; }
        }
        s = 1.f / (1.f + expf(-z1));
    }

    // ---- per-CTA vote: exact fallback if any pixel too close to call ----
    if (__syncthreads_or((z1 - z2) < 1e-4f)) {
        for (int i = t; i < 2048; i += NTHR) {
            int c = i >> 4, o = i & 15;
            fw2[i] = fw[o * CIN + c];
        }
        __syncthreads();

        unsigned long long fhi[8], flo[8];
        if (t < 256) {
            #pragma unroll
            for (int j = 0; j < 8; j++) { fhi[j] = pk2(OFFSET_F, OFFSET_F); flo[j] = 0ull; }
            const float* xf = x + (size_t)batch * COUT * HW
                                + (size_t)(gx * 16 + apr) * WIDTH + (gy * 16 + apc);
            #pragma unroll 4
            for (int c = 0; c < CIN; c++) {
                float x1 = __ldg(xf + (size_t)c * HW);
                unsigned long long x1d = pk2(x1, x1);
                const ulonglong2* wf = (const ulonglong2*)(fw2 + c * 16);
                #pragma unroll
                for (int j = 0; j < 4; j++) {
                    ulonglong2 a = wf[j];
                    dfacc2(fhi[2*j],   flo[2*j],   x1d, a.x);
                    dfacc2(fhi[2*j+1], flo[2*j+1], x1d, a.y);
                }
            }
        }
        __syncthreads();     // all fs readers done before fp64 overwrite
        if (t < 256) {
            #pragma unroll
            for (int j = 0; j < 8; j++) {
                float2 h = upk(fhi[j]), l = upk(flo[j]);
                fsd[(2*j)   * FSTR + t] =
                    ((double)__fadd_rn(h.x, -OFFSET_F) + (double)l.x) + (double)fbs[2*j];
                fsd[(2*j+1) * FSTR + t] =
                    ((double)__fadd_rn(h.y, -OFFSET_F) + (double)l.y) + (double)fbs[2*j+1];
            }
        }
        __syncthreads();

        for (int it = t; it < 784; it += NTHR) {
            int m = it >> 4, cc = it & 15;
            int i = m / 7, jj = m - i * 7;
            double ssum = 0.0;
            for (int r = SEG_S[i]; r < SEG_E[i]; r++)
                for (int q = SEG_S[jj]; q < SEG_E[jj]; q++)
                    ssum += fsd[cc * FSTR + r * 16 + q];
            cfd[it] = ssum * (double)SEG_I[i] * (double)SEG_I[jj];
        }
        __syncthreads();
        if (t < 49) {
            double ss = 0.0;
            #pragma unroll
            for (int cc = 0; cc < 16; cc++) { double v = cfd[t*16+cc]; ss = fma(v, v, ss); }
            double inv = 1.0 / fmax(sqrt(ss), 1e-12);
            #pragma unroll
            for (int cc = 0; cc < 16; cc++) cfd[t*16+cc] *= inv;
        }
        __syncthreads();

        if (t < 256) {
            double invf;
            {
                double ss = 0.0;
                #pragma unroll
                for (int cc = 0; cc < 16; cc++) {
                    double v = fsd[cc * FSTR + t];
                    ss = fma(v, v, ss);
                }
                invf = 1.0 / fmax(sqrt(ss), 1e-12);
            }
            const double alpha = (double)alphaf;
            const double beta  = (double)betaf;

            float mx32 = -1e30f;
            for (int m = 0; m < 49; m++) {
                const float4* cr = (const float4*)(cf32 + m * 16);
                float dot = 0.f;
                #pragma unroll
                for (int q = 0; q < 4; q++) {
                    float4 w = cr[q];
                    dot = __fmaf_rn(w.x, ffn[4*q+0], dot);
                    dot = __fmaf_rn(w.y, ffn[4*q+1], dot);
                    dot = __fmaf_rn(w.z, ffn[4*q+2], dot);
                    dot = __fmaf_rn(w.w, ffn[4*q+3], dot);
                }
                mx32 = fmaxf(mx32, dot);
            }
            const float thr = mx32 - 1e-4f;
            double dz1 = -1e300, dz2 = -1e300, dz3 = -1e300;
            int m1 = 0, m2 = 0, m3 = 0;
            for (int m = 0; m < 49; m++) {
                const float4* cr = (const float4*)(cf32 + m * 16);
                float dot = 0.f;
                #pragma unroll
                for (int q = 0; q < 4; q++) {
                    float4 w = cr[q];
                    dot = __fmaf_rn(w.x, ffn[4*q+0], dot);
                    dot = __fmaf_rn(w.y, ffn[4*q+1], dot);
                    dot = __fmaf_rn(w.z, ffn[4*q+2], dot);
                    dot = __fmaf_rn(w.w, ffn[4*q+3], dot);
                }
                if (dot >= thr) {
                    double dd = 0.0;
                    #pragma unroll
                    for (int cc = 0; cc < 16; cc++)
                        dd = fma(cfd[m*16+cc], fsd[cc * FSTR + t], dd);
                    double z = beta + alpha * (dd * invf);
                    if (z > dz1)      { dz3 = dz2; m3 = m2; dz2 = dz1; m2 = m1; dz1 = z; m1 = m; }
                    else if (z > dz2) { dz3 = dz2; m3 = m2; dz2 = z;  m2 = m; }
                    else if (z > dz3) { dz3 = z;  m3 = m; }
                }
            }
            float s1f = (float)(1.0 / (1.0 + exp(-dz1)));
            bm = m1;
            if (dz1 - dz2 < 1e-5) {
                float s2f = (float)(1.0 / (1.0 + exp(-dz2)));
                if (s2f == s1f && m2 < bm) bm = m2;
                if (dz1 - dz3 < 1e-5) {
                    float s3f = (float)(1.0 / (1.0 + exp(-dz3)));
                    if (s3f == s1f && m3 < bm) bm = m3;
                }
            }
            s = s1f;
        }
        __syncthreads();
    }

    // ---- aggregate (lower 256 threads) ----
    if (t < 256) {
        atomicAdd(&agd[bm], s);
        #pragma unroll
        for (int cc = 0; cc < 16; cc++)
            atomicAdd(&agn[bm * 16 + cc], s * vs[cc * FSTR + t]);
    }
    __syncthreads();

    // ---- merge agg; persist per-pixel (s, bm); fs region is dead now ----
    for (int it = t; it < 784; it += NTHR) {
        int m = it >> 4;
        agn[it] = (agn[it] + vc[it]) / (agd[m] + 1.f);
    }
    if (t < 256) { sp[t] = s; bmi[t] = bm; }
    __syncthreads();

    // ---- load p weights as-is ([o][cc] row-major) into wbuf ----
    for (int i = t; i < 1024; i += NTHR)
        ((float4*)pws)[i] = ((const float4*)pw)[i];
    __syncthreads();

    // ---- Stage D (algebraic): y[o][n] = s_n * P[o][bm_n] + pb[o] ----
    // Two o-tiles of 128; P tile [49][PSTR] lives in the dead fs region.
    const int npair = t & 127;           // pixel pair id
    const int ogrp  = t >> 7;            // 0..3 -> 32-o chunk
    const int n0 = npair * 2;
    float* yb0 = out + (size_t)batch * COUT * HW
                     + (size_t)(gx * 16 + (n0 >> 4)) * WIDTH + (gy * 16 + (n0 & 15));

    #pragma unroll
    for (int tile = 0; tile < 2; tile++) {
        // P GEMM: P[m][ol] = agg[m] . pw[tile*128 + ol]
        for (int idx = t; idx < 49 * 128; idx += NTHR) {
            int m = idx >> 7, ol = idx & 127;
            const ulonglong2* ar = (const ulonglong2*)(agn + m * 16);
            const ulonglong2* wr = (const ulonglong2*)(pws + (tile * 128 + ol) * 16);
            unsigned long long a = 0ull;
            ulonglong2 a0 = ar[0], w0 = wr[0];
            a = ffma2(a0.x, w0.x, a);
            a = ffma2(a0.y, w0.y, a);
            ulonglong2 a1 = ar[1], w1 = wr[1];
            a = ffma2(a1.x, w1.x, a);
            a = ffma2(a1.y, w1.y, a);
            ulonglong2 a2 = ar[2], w2 = wr[2];
            a = ffma2(a2.x, w2.x, a);
            a = ffma2(a2.y, w2.y, a);
            ulonglong2 a3 = ar[3], w3 = wr[3];
            a = ffma2(a3.x, w3.x, a);
            a = ffma2(a3.y, w3.y, a);
            float2 f = upk(a);
            Pm[m * PSTR + ol] = f.x + f.y;
        }
        __syncthreads();

        // epilogue: this thread covers 32 o-values for its pixel pair
        {
            float s0 = sp[n0], s1 = sp[n0 + 1];
            const float* P0 = Pm + bmi[n0] * PSTR + ogrp * 32;
            const float* P1 = Pm + bmi[n0 + 1] * PSTR + ogrp * 32;
            const float* pbo = pbs + tile * 128 + ogrp * 32;
            float* yo = yb0 + (size_t)(tile * 128 + ogrp * 32) * HW;
            #pragma unroll 8
            for (int i = 0; i < 32; i++) {
                float pbv = pbo[i];
                float2 r;
                r.x = __fmaf_rn(s0, P0[i], pbv);
                r.y = __fmaf_rn(s1, P1[i], pbv);
                *(float2*)(yo + (size_t)i * HW) = r;
            }
        }
        __syncthreads();   // P consumed before next tile overwrites
    }
}

extern "C" void kernel_launch(void* const* d_in, const int* in_sizes, int n_in,
                              void* d_out, int out_size) {
    const float* x   = (const float*)d_in[0];
    const float* fw  = (const float*)d_in[1];
    const float* fb  = (const float*)d_in[2];
    const float* vw  = (const float*)d_in[3];
    const float* vb  = (const float*)d_in[4];
    const float* pw  = (const float*)d_in[5];
    const float* pb  = (const float*)d_in[6];
    const float* sa  = (const float*)d_in[7];
    const float* sb  = (const float*)d_in[8];
    float* out = (float*)d_out;

    cudaFuncSetAttribute(lc_kernel, cudaFuncAttributeMaxDynamicSharedMemorySize,
                         SMEM_BYTES);
    lc_kernel<<<NBLK, NTHR, SMEM_BYTES>>>(x, fw, fb, vw, vb, pw, pb, sa, sb, out);
}

// round 11
// speedup vs baseline: 1.5186x; 1.1518x over previous
#include <cuda_runtime.h>
#include <math.h>

// Problem constants
#define CIN    128
#define CMID   16
#define COUT   256
#define HW     12544
#define WIDTH  112
#define NBLK   784
#define NTHR   512

// Pooling segments 16 -> 7 (overlapping avg pool)
__constant__ int   SEG_S[7] = {0, 2, 4, 6, 9, 11, 13};
__constant__ int   SEG_E[7] = {3, 5, 7, 10, 12, 14, 16};
__constant__ float SEG_I[7] = {1.f/3.f, 1.f/3.f, 1.f/3.f, 0.25f, 1.f/3.f, 1.f/3.f, 1.f/3.f};

// ---- packed f32x2 helpers (sm_103a, PTX-only) ----
__device__ __forceinline__ unsigned long long pk2(float a, float b) {
    unsigned long long r;
    asm("mov.b64 %0, {%1, %2};" : "=l"(r) : "f"(a), "f"(b));
    return r;
}
__device__ __forceinline__ unsigned long long ffma2(unsigned long long a,
                                                    unsigned long long b,
                                                    unsigned long long c) {
    unsigned long long d;
    asm("fma.rn.f32x2 %0, %1, %2, %3;" : "=l"(d) : "l"(a), "l"(b), "l"(c));
    return d;
}
__device__ __forceinline__ unsigned long long fmul2(unsigned long long a,
                                                    unsigned long long b) {
    unsigned long long d;
    asm("mul.rn.f32x2 %0, %1, %2;" : "=l"(d) : "l"(a), "l"(b));
    return d;
}
__device__ __forceinline__ unsigned long long fadd2(unsigned long long a,
                                                    unsigned long long b) {
    unsigned long long d;
    asm("add.rn.f32x2 %0, %1, %2;" : "=l"(d) : "l"(a), "l"(b));
    return d;
}
__device__ __forceinline__ float2 upk(unsigned long long v) {
    float2 f;
    asm("mov.b64 {%0, %1}, %2;" : "=f"(f.x), "=f"(f.y) : "l"(v));
    return f;
}

#define SGNMASK 0x8000000080000000ULL
#define OFFSET_F 16384.0f

// Exact compensated accumulate (fallback path only).
__device__ __forceinline__ void dfacc2(unsigned long long& hi, unsigned long long& lo,
                                       unsigned long long xd, unsigned long long w) {
    unsigned long long ph = fmul2(xd, w);
    unsigned long long pl = ffma2(xd, w, ph ^ SGNMASK);
    unsigned long long s  = fadd2(hi, ph);
    unsigned long long d  = fadd2(hi, s ^ SGNMASK);
    unsigned long long e  = fadd2(d, ph);
    lo = fadd2(lo, fadd2(e, pl));
    hi = s;
}

// Shared memory byte-offsets
#define FSTR 257     // stride (floats for fs/vs, doubles for fsd)
#define MSTR 18      // midT stride (floats), conflict-dodged
#define OFF_R0    0                          // union: fs float[16*257] (common)
                                             //        fsd double[16*257] (fallback)
                                             //        midT float[256*18] (stage D)
#define OFF_CFD   (OFF_R0 + 16*FSTR*8)       // double[784] exact centers (fallback)
#define OFF_WBUF  (OFF_CFD + 784*8)          // float[4096] time-shared:
                                             //  A: wsf[0:2048] wsv[2048:4096]
                                             //  B/C: vc[0:784] cf32[784:1568]
                                             //  fallback: fw2[1568:3616]
                                             //  D: pwt2[0:4096] (pw as-is, [o][cc])
#define OFF_VS    (OFF_WBUF + 4096*4)        // float[16*257] v features
#define OFF_AGN   (OFF_VS  + 16*FSTR*4)      // float[784]
#define OFF_AGD   (OFF_AGN + 784*4)          // float[52]
#define OFF_FBS   (OFF_AGD + 52*4)           // float[16]
#define OFF_VBS   (OFF_FBS + 16*4)           // float[16]
#define OFF_PBS   (OFF_VBS + 16*4)           // float[256]
#define OFF_ZB1   (OFF_PBS + 256*4)          // float[512] half top-1 z  (later: s)
#define OFF_ZB2   (OFF_ZB1 + 512*4)          // float[512] half top-2 z
#define OFF_BMB   (OFF_ZB2 + 512*4)          // int[512]   half argmax   (later: bm)
#define SMEM_BYTES (OFF_BMB + 512*4)         // 82,640 B -> 2 CTAs/SM @512thr

extern "C" __global__ void __launch_bounds__(NTHR, 2)
lc_kernel(const float* __restrict__ x,   const float* __restrict__ fw,
          const float* __restrict__ fb,  const float* __restrict__ vw,
          const float* __restrict__ vb,  const float* __restrict__ pw,
          const float* __restrict__ pbg, const float* __restrict__ salpha,
          const float* __restrict__ sbeta, float* __restrict__ out)
{
    extern __shared__ char smraw[];
    float*  fs   = (float*)(smraw + OFF_R0);
    double* fsd  = (double*)(smraw + OFF_R0);
    float*  midT = (float*)(smraw + OFF_R0);
    double* cfd  = (double*)(smraw + OFF_CFD);
    float*  wbuf = (float*)(smraw + OFF_WBUF);
    float*  vs   = (float*)(smraw + OFF_VS);
    float*  agn  = (float*)(smraw + OFF_AGN);
    float*  agd  = (float*)(smraw + OFF_AGD);
    float*  fbs  = (float*)(smraw + OFF_FBS);
    float*  vbs  = (float*)(smraw + OFF_VBS);
    float*  pbs  = (float*)(smraw + OFF_PBS);
    float*  zb1  = (float*)(smraw + OFF_ZB1);
    float*  zb2  = (float*)(smraw + OFF_ZB2);
    int*    bmb  = (int*)(smraw + OFF_BMB);
    float*  wsf  = wbuf;
    float*  wsv  = wbuf + 2048;
    float*  vc   = wbuf;
    float*  cf32 = wbuf + 784;
    float*  fw2  = wbuf + 1568;
    float*  pwt2 = wbuf;

    const int t = threadIdx.x;
    const int b = blockIdx.x;
    const int batch = b / 49;
    const int g = b - batch * 49;
    const int gx = g / 7, gy = g - (g / 7) * 7;

    // ---- stage A weights + biases into smem ----
    for (int i = t; i < 2048; i += NTHR) {
        int c = i >> 4, o = i & 15;
        wsf[i] = fw[o * CIN + c];
        wsv[i] = vw[o * CIN + c];
    }
    if (t < 16) { fbs[t] = fb[t]; vbs[t] = vb[t]; }
    if (t < 256) pbs[t] = pbg[t];
    for (int i = t; i < 784; i += NTHR) agn[i] = 0.f;
    if (t < 49) agd[t] = 0.f;
    __syncthreads();

    // ---- Stage A: warps 0-7 -> f, warps 8-15 -> v (1 pixel, 128 ch each) ----
    const int px  = t & 255;             // pixel
    const int prj = t >> 8;              // 0 = f, 1 = v
    const int apr = px >> 4, apc = px & 15;
    const float* xa = x + (size_t)batch * COUT * HW + (size_t)prj * CIN * HW
                        + (size_t)(gx * 16 + apr) * WIDTH + (gy * 16 + apc);
    const float* wsel = prj ? wsv : wsf;
    {
        unsigned long long acc[8];
        #pragma unroll
        for (int j = 0; j < 8; j++) acc[j] = 0ull;
        #pragma unroll 8
        for (int c = 0; c < CIN; c++) {
            float xv = __ldg(xa + (size_t)c * HW);
            unsigned long long xd = pk2(xv, xv);
            const ulonglong2* wr = (const ulonglong2*)(wsel + c * 16);
            #pragma unroll
            for (int j = 0; j < 4; j++) {
                ulonglong2 a = wr[j];
                acc[2*j]   = ffma2(xd, a.x, acc[2*j]);
                acc[2*j+1] = ffma2(xd, a.y, acc[2*j+1]);
            }
        }
        float* dst = prj ? vs : fs;
        const float* bsel = prj ? vbs : fbs;
        #pragma unroll
        for (int j = 0; j < 8; j++) {
            float2 v = upk(acc[j]);
            dst[(2*j)   * FSTR + px] = v.x + bsel[2*j];
            dst[(2*j+1) * FSTR + px] = v.y + bsel[2*j+1];
        }
    }
    __syncthreads();

    // ---- Stage B: fp32 pooling (centers cf32, value centers vc) ----
    for (int it = t; it < 1568; it += NTHR) {
        int half = it >= 784;
        int rem = half ? it - 784 : it;
        int m = rem >> 4, cc = rem & 15;
        int i = m / 7, jj = m - i * 7;
        const float* src = half ? vs : fs;
        float ssum = 0.f;
        for (int r = SEG_S[i]; r < SEG_E[i]; r++)
            for (int q = SEG_S[jj]; q < SEG_E[jj]; q++)
                ssum += src[cc * FSTR + r * 16 + q];
        ssum *= SEG_I[i] * SEG_I[jj];
        if (half) vc[rem] = ssum; else cf32[rem] = ssum;
    }
    __syncthreads();

    if (t < 49) {
        float ss = 0.f;
        #pragma unroll
        for (int cc = 0; cc < 16; cc++) {
            float v = cf32[t*16+cc];
            ss = __fmaf_rn(v, v, ss);
        }
        float inv = 1.f / fmaxf(sqrtf(ss), 1e-12f);
        #pragma unroll
        for (int cc = 0; cc < 16; cc++) cf32[t*16+cc] *= inv;
    }
    __syncthreads();

    // ---- Stage C: ALL 512 threads; each covers half the clusters for pixel px ----
    const float alphaf = __ldg(salpha);
    const float betaf  = __ldg(sbeta);
    float ffn[16];
    {
        float ss = 0.f;
        #pragma unroll
        for (int cc = 0; cc < 16; cc++) {
            float v = fs[cc * FSTR + px];
            ffn[cc] = v;
            ss = __fmaf_rn(v, v, ss);
        }
        float inv = 1.f / fmaxf(sqrtf(ss), 1e-12f);
        #pragma unroll
        for (int cc = 0; cc < 16; cc++) ffn[cc] *= inv;

        float z1h = -1e30f, z2h = -1e30f;
        int bmh = 0;
        const int mstart = prj ? 25 : 0;
        const int mend   = prj ? 49 : 25;
        for (int m = mstart; m < mend; m++) {
            const float4* cr = (const float4*)(cf32 + m * 16);
            float dot = 0.f;
            #pragma unroll
            for (int q = 0; q < 4; q++) {
                float4 w = cr[q];
                dot = __fmaf_rn(w.x, ffn[4*q+0], dot);
                dot = __fmaf_rn(w.y, ffn[4*q+1], dot);
                dot = __fmaf_rn(w.z, ffn[4*q+2], dot);
                dot = __fmaf_rn(w.w, ffn[4*q+3], dot);
            }
            float z = betaf + alphaf * dot;
            if (z > z1h) { z2h = z1h; z1h = z; bmh = m; }
            else if (z > z2h) { z2h = z; }
        }
        zb1[t] = z1h; zb2[t] = z2h; bmb[t] = bmh;
    }
    __syncthreads();

    // ---- merge halves (lower 256 threads own the decision) ----
    float z1 = 1e30f, z2 = 0.f;          // upper threads: gap huge -> no vote
    int bm = 0;
    float s = 0.f;
    if (t < 256) {
        float a1 = zb1[t],       a2 = zb2[t];       int abm = bmb[t];
        float b1 = zb1[t + 256], b2 = zb2[t + 256]; int bbm = bmb[t + 256];
        if (a1 >= b1) { z1 = a1; bm = abm; z2 = fmaxf(a2, b1); }
        else          { z1 = b1; bm = bbm; z2 = fmaxf(b2, a1); }
        s = 1.f / (1.f + expf(-z1));
    }

    // ---- per-CTA vote: exact fallback if any pixel too close to call ----
    if (__syncthreads_or((t < 256) && (z1 - z2) < 1e-4f)) {
        for (int i = t; i < 2048; i += NTHR) {
            int c = i >> 4, o = i & 15;
            fw2[i] = fw[o * CIN + c];
        }
        __syncthreads();

        unsigned long long fhi[8], flo[8];
        if (t < 256) {
            #pragma unroll
            for (int j = 0; j < 8; j++) { fhi[j] = pk2(OFFSET_F, OFFSET_F); flo[j] = 0ull; }
            const float* xf = x + (size_t)batch * COUT * HW
                                + (size_t)(gx * 16 + apr) * WIDTH + (gy * 16 + apc);
            #pragma unroll 4
            for (int c = 0; c < CIN; c++) {
                float x1 = __ldg(xf + (size_t)c * HW);
                unsigned long long x1d = pk2(x1, x1);
                const ulonglong2* wf = (const ulonglong2*)(fw2 + c * 16);
                #pragma unroll
                for (int j = 0; j < 4; j++) {
                    ulonglong2 a = wf[j];
                    dfacc2(fhi[2*j],   flo[2*j],   x1d, a.x);
                    dfacc2(fhi[2*j+1], flo[2*j+1], x1d, a.y);
                }
            }
        }
        __syncthreads();     // all fs readers done before fp64 overwrite
        if (t < 256) {
            #pragma unroll
            for (int j = 0; j < 8; j++) {
                float2 h = upk(fhi[j]), l = upk(flo[j]);
                fsd[(2*j)   * FSTR + t] =
                    ((double)__fadd_rn(h.x, -OFFSET_F) + (double)l.x) + (double)fbs[2*j];
                fsd[(2*j+1) * FSTR + t] =
                    ((double)__fadd_rn(h.y, -OFFSET_F) + (double)l.y) + (double)fbs[2*j+1];
            }
        }
        __syncthreads();

        for (int it = t; it < 784; it += NTHR) {
            int m = it >> 4, cc = it & 15;
            int i = m / 7, jj = m - i * 7;
            double ssum = 0.0;
            for (int r = SEG_S[i]; r < SEG_E[i]; r++)
                for (int q = SEG_S[jj]; q < SEG_E[jj]; q++)
                    ssum += fsd[cc * FSTR + r * 16 + q];
            cfd[it] = ssum * (double)SEG_I[i] * (double)SEG_I[jj];
        }
        __syncthreads();
        if (t < 49) {
            double ss = 0.0;
            #pragma unroll
            for (int cc = 0; cc < 16; cc++) { double v = cfd[t*16+cc]; ss = fma(v, v, ss); }
            double inv = 1.0 / fmax(sqrt(ss), 1e-12);
            #pragma unroll
            for (int cc = 0; cc < 16; cc++) cfd[t*16+cc] *= inv;
        }
        __syncthreads();

        if (t < 256) {
            double invf;
            {
                double ss = 0.0;
                #pragma unroll
                for (int cc = 0; cc < 16; cc++) {
                    double v = fsd[cc * FSTR + t];
                    ss = fma(v, v, ss);
                }
                invf = 1.0 / fmax(sqrt(ss), 1e-12);
            }
            const double alpha = (double)alphaf;
            const double beta  = (double)betaf;

            float mx32 = -1e30f;
            for (int m = 0; m < 49; m++) {
                const float4* cr = (const float4*)(cf32 + m * 16);
                float dot = 0.f;
                #pragma unroll
                for (int q = 0; q < 4; q++) {
                    float4 w = cr[q];
                    dot = __fmaf_rn(w.x, ffn[4*q+0], dot);
                    dot = __fmaf_rn(w.y, ffn[4*q+1], dot);
                    dot = __fmaf_rn(w.z, ffn[4*q+2], dot);
                    dot = __fmaf_rn(w.w, ffn[4*q+3], dot);
                }
                mx32 = fmaxf(mx32, dot);
            }
            const float thr = mx32 - 1e-4f;
            double dz1 = -1e300, dz2 = -1e300, dz3 = -1e300;
            int m1 = 0, m2 = 0, m3 = 0;
            for (int m = 0; m < 49; m++) {
                const float4* cr = (const float4*)(cf32 + m * 16);
                float dot = 0.f;
                #pragma unroll
                for (int q = 0; q < 4; q++) {
                    float4 w = cr[q];
                    dot = __fmaf_rn(w.x, ffn[4*q+0], dot);
                    dot = __fmaf_rn(w.y, ffn[4*q+1], dot);
                    dot = __fmaf_rn(w.z, ffn[4*q+2], dot);
                    dot = __fmaf_rn(w.w, ffn[4*q+3], dot);
                }
                if (dot >= thr) {
                    double dd = 0.0;
                    #pragma unroll
                    for (int cc = 0; cc < 16; cc++)
                        dd = fma(cfd[m*16+cc], fsd[cc * FSTR + t], dd);
                    double z = beta + alpha * (dd * invf);
                    if (z > dz1)      { dz3 = dz2; m3 = m2; dz2 = dz1; m2 = m1; dz1 = z; m1 = m; }
                    else if (z > dz2) { dz3 = dz2; m3 = m2; dz2 = z;  m2 = m; }
                    else if (z > dz3) { dz3 = z;  m3 = m; }
                }
            }
            float s1f = (float)(1.0 / (1.0 + exp(-dz1)));
            bm = m1;
            if (dz1 - dz2 < 1e-5) {
                float s2f = (float)(1.0 / (1.0 + exp(-dz2)));
                if (s2f == s1f && m2 < bm) bm = m2;
                if (dz1 - dz3 < 1e-5) {
                    float s3f = (float)(1.0 / (1.0 + exp(-dz3)));
                    if (s3f == s1f && m3 < bm) bm = m3;
                }
            }
            s = s1f;
        }
        __syncthreads();
    }

    // ---- share (s, bm) so both halves can split the atomic work ----
    if (t < 256) { zb1[t] = s; bmb[t] = bm; }
    __syncthreads();

    // ---- aggregate: lower does agd + cc 0-7, upper does cc 8-15 ----
    {
        float sv = zb1[px];
        int bmv = bmb[px];
        if (t < 256) atomicAdd(&agd[bmv], sv);
        const int cc0 = prj ? 8 : 0;
        #pragma unroll
        for (int cc = 0; cc < 8; cc++)
            atomicAdd(&agn[bmv * 16 + cc0 + cc], sv * vs[(cc0 + cc) * FSTR + px]);
    }
    __syncthreads();

    for (int it = t; it < 784; it += NTHR) {
        int m = it >> 4;
        agn[it] = (agn[it] + vc[it]) / (agd[m] + 1.f);
    }
    __syncthreads();

    // ---- write midT[n][cc] (transposed; fs region is dead now) ----
    if (t < 256) {
        #pragma unroll
        for (int q = 0; q < 8; q++) {
            float a = s * agn[bm * 16 + 2*q];
            float c = s * agn[bm * 16 + 2*q + 1];
            *(unsigned long long*)(midT + t * MSTR + 2*q) = pk2(a, c);
        }
    }
    // ---- load p weights as-is ([o][cc], row-major) ----
    for (int i = t; i < 1024; i += NTHR)
        ((float4*)pwt2)[i] = ((const float4*)pw)[i];
    __syncthreads();

    // ---- Stage D: thread = (o-group of 64) x (pixel pair); GEMM from regs ----
    {
        const int nid = t & 127, oid = t >> 7;
        const int n0 = 2 * nid;
        unsigned long long midA[8], midB[8];
        #pragma unroll
        for (int q = 0; q < 8; q++) {
            midA[q] = *(const unsigned long long*)(midT + n0 * MSTR + 2*q);
            midB[q] = *(const unsigned long long*)(midT + (n0 + 1) * MSTR + 2*q);
        }
        float* yb = out + (size_t)batch * COUT * HW
                        + (size_t)(gx * 16 + (n0 >> 4)) * WIDTH + (gy * 16 + (n0 & 15));
        const int obase = oid << 6;
        #pragma unroll 4
        for (int i = 0; i < 64; i++) {
            const int o = obase + i;
            const ulonglong2* wr = (const ulonglong2*)(pwt2 + o * 16);
            unsigned long long aA = 0ull, aB = 0ull;
            #pragma unroll
            for (int q = 0; q < 2; q++) {
                ulonglong2 w = wr[q];
                aA = ffma2(w.x, midA[2*q],   aA);
                aA = ffma2(w.y, midA[2*q+1], aA);
                aB = ffma2(w.x, midB[2*q],   aB);
                aB = ffma2(w.y, midB[2*q+1], aB);
            }
            #pragma unroll
            for (int q = 2; q < 4; q++) {
                ulonglong2 w = wr[q];
                aA = ffma2(w.x, midA[2*q],   aA);
                aA = ffma2(w.y, midA[2*q+1], aA);
                aB = ffma2(w.x, midB[2*q],   aB);
                aB = ffma2(w.y, midB[2*q+1], aB);
            }
            float2 fa = upk(aA), fbv = upk(aB);
            float pbo = pbs[o];
            float2 r;
            r.x = pbo + fa.x + fa.y;
            r.y = pbo + fbv.x + fbv.y;
            *(float2*)(yb + (size_t)o * HW) = r;
        }
    }
}

extern "C" void kernel_launch(void* const* d_in, const int* in_sizes, int n_in,
                              void* d_out, int out_size) {
    const float* x   = (const float*)d_in[0];
    const float* fw  = (const float*)d_in[1];
    const float* fb  = (const float*)d_in[2];
    const float* vw  = (const float*)d_in[3];
    const float* vb  = (const float*)d_in[4];
    const float* pw  = (const float*)d_in[5];
    const float* pb  = (const float*)d_in[6];
    const float* sa  = (const float*)d_in[7];
    const float* sb  = (const float*)d_in[8];
    float* out = (float*)d_out;

    cudaFuncSetAttribute(lc_kernel, cudaFuncAttributeMaxDynamicSharedMemorySize,
                         SMEM_BYTES);
    lc_kernel<<<NBLK, NTHR, SMEM_BYTES>>>(x, fw, fb, vw, vb, pw, pb, sa, sb, out);
}

// round 12
// speedup vs baseline: 1.5328x; 1.0094x over previous
#include <cuda_runtime.h>
#include <math.h>

// Problem constants
#define CIN    128
#define CMID   16
#define COUT   256
#define HW     12544
#define WIDTH  112
#define NBLK   784
#define NTHR   512

// Pooling segments 16 -> 7 (overlapping avg pool)
__constant__ int   SEG_S[7] = {0, 2, 4, 6, 9, 11, 13};
__constant__ int   SEG_E[7] = {3, 5, 7, 10, 12, 14, 16};
__constant__ float SEG_I[7] = {1.f/3.f, 1.f/3.f, 1.f/3.f, 0.25f, 1.f/3.f, 1.f/3.f, 1.f/3.f};

// ---- packed f32x2 helpers (sm_103a, PTX-only) ----
__device__ __forceinline__ unsigned long long pk2(float a, float b) {
    unsigned long long r;
    asm("mov.b64 %0, {%1, %2};" : "=l"(r) : "f"(a), "f"(b));
    return r;
}
__device__ __forceinline__ unsigned long long ffma2(unsigned long long a,
                                                    unsigned long long b,
                                                    unsigned long long c) {
    unsigned long long d;
    asm("fma.rn.f32x2 %0, %1, %2, %3;" : "=l"(d) : "l"(a), "l"(b), "l"(c));
    return d;
}
__device__ __forceinline__ unsigned long long fmul2(unsigned long long a,
                                                    unsigned long long b) {
    unsigned long long d;
    asm("mul.rn.f32x2 %0, %1, %2;" : "=l"(d) : "l"(a), "l"(b));
    return d;
}
__device__ __forceinline__ unsigned long long fadd2(unsigned long long a,
                                                    unsigned long long b) {
    unsigned long long d;
    asm("add.rn.f32x2 %0, %1, %2;" : "=l"(d) : "l"(a), "l"(b));
    return d;
}
__device__ __forceinline__ float2 upk(unsigned long long v) {
    float2 f;
    asm("mov.b64 {%0, %1}, %2;" : "=f"(f.x), "=f"(f.y) : "l"(v));
    return f;
}

#define SGNMASK 0x8000000080000000ULL
#define OFFSET_F 16384.0f

// Exact compensated accumulate (fallback path only).
__device__ __forceinline__ void dfacc2(unsigned long long& hi, unsigned long long& lo,
                                       unsigned long long xd, unsigned long long w) {
    unsigned long long ph = fmul2(xd, w);
    unsigned long long pl = ffma2(xd, w, ph ^ SGNMASK);
    unsigned long long s  = fadd2(hi, ph);
    unsigned long long d  = fadd2(hi, s ^ SGNMASK);
    unsigned long long e  = fadd2(d, ph);
    lo = fadd2(lo, fadd2(e, pl));
    hi = s;
}

// Shared memory byte-offsets
#define FSTR 257     // stride (floats for fs/vs, doubles for fsd)
#define MSTR 18      // midT stride (floats), conflict-dodged
#define OFF_R0    0                          // union: fs float[16*257] (common)
                                             //        fsd double[16*257] (fallback)
                                             //        midT float[256*18] (stage D)
#define OFF_CFD   (OFF_R0 + 16*FSTR*8)       // double[784] exact centers (fallback)
#define OFF_WBUF  (OFF_CFD + 784*8)          // float[4096] time-shared:
                                             //  A: wsf[0:2048] wsv[2048:4096]
                                             //  B/C: vc[0:784] cf32[784:1568]
                                             //  fallback: fw2[1568:3616]
#define OFF_VS    (OFF_WBUF + 4096*4)        // float[16*257] v features
                                             //  stage D: pwt2[0:4096] (pw [o][cc])
#define OFF_AGN   (OFF_VS  + 16*FSTR*4)      // float[784]
#define OFF_AGD   (OFF_AGN + 784*4)          // float[52]
#define OFF_FBS   (OFF_AGD + 52*4)           // float[16]
#define OFF_VBS   (OFF_FBS + 16*4)           // float[16]
#define OFF_PBS   (OFF_VBS + 16*4)           // float[256]
#define OFF_ZB1   (OFF_PBS + 256*4)          // float[512] half top-1 z  (later: s)
#define OFF_ZB2   (OFF_ZB1 + 512*4)          // float[512] half top-2 z
#define OFF_BMB   (OFF_ZB2 + 512*4)          // int[512]   half argmax   (later: bm)
#define SMEM_BYTES (OFF_BMB + 512*4)         // 82,640 B -> 2 CTAs/SM @512thr

extern "C" __global__ void __launch_bounds__(NTHR, 2)
lc_kernel(const float* __restrict__ x,   const float* __restrict__ fw,
          const float* __restrict__ fb,  const float* __restrict__ vw,
          const float* __restrict__ vb,  const float* __restrict__ pw,
          const float* __restrict__ pbg, const float* __restrict__ salpha,
          const float* __restrict__ sbeta, float* __restrict__ out)
{
    extern __shared__ char smraw[];
    float*  fs   = (float*)(smraw + OFF_R0);
    double* fsd  = (double*)(smraw + OFF_R0);
    float*  midT = (float*)(smraw + OFF_R0);
    double* cfd  = (double*)(smraw + OFF_CFD);
    float*  wbuf = (float*)(smraw + OFF_WBUF);
    float*  vs   = (float*)(smraw + OFF_VS);
    float*  agn  = (float*)(smraw + OFF_AGN);
    float*  agd  = (float*)(smraw + OFF_AGD);
    float*  fbs  = (float*)(smraw + OFF_FBS);
    float*  vbs  = (float*)(smraw + OFF_VBS);
    float*  pbs  = (float*)(smraw + OFF_PBS);
    float*  zb1  = (float*)(smraw + OFF_ZB1);
    float*  zb2  = (float*)(smraw + OFF_ZB2);
    int*    bmb  = (int*)(smraw + OFF_BMB);
    float*  wsf  = wbuf;
    float*  wsv  = wbuf + 2048;
    float*  vc   = wbuf;
    float*  cf32 = wbuf + 784;
    float*  fw2  = wbuf + 1568;
    float*  pwt2 = vs;               // stage D: vs region is dead after atomics

    const int t = threadIdx.x;
    const int b = blockIdx.x;
    const int batch = b / 49;
    const int g = b - batch * 49;
    const int gx = g / 7, gy = g - (g / 7) * 7;

    // ---- stage A weights + biases into smem ----
    for (int i = t; i < 2048; i += NTHR) {
        int c = i >> 4, o = i & 15;
        wsf[i] = fw[o * CIN + c];
        wsv[i] = vw[o * CIN + c];
    }
    if (t < 16) { fbs[t] = fb[t]; vbs[t] = vb[t]; }
    if (t < 256) pbs[t] = pbg[t];
    for (int i = t; i < 784; i += NTHR) agn[i] = 0.f;
    if (t < 49) agd[t] = 0.f;
    __syncthreads();

    // ---- Stage A: warps 0-7 -> f, warps 8-15 -> v; software-pipelined x loads ----
    const int px  = t & 255;             // pixel
    const int prj = t >> 8;              // 0 = f, 1 = v
    const int apr = px >> 4, apc = px & 15;
    const float* xa = x + (size_t)batch * COUT * HW + (size_t)prj * CIN * HW
                        + (size_t)(gx * 16 + apr) * WIDTH + (gy * 16 + apc);
    const float* wsel = prj ? wsv : wsf;
    {
        unsigned long long acc[8];
        float xc[8], xn[8];
        #pragma unroll
        for (int j = 0; j < 8; j++) acc[j] = 0ull;
        #pragma unroll
        for (int j = 0; j < 8; j++) xc[j] = __ldg(xa + (size_t)j * HW);

        for (int cb = 0; cb < CIN - 8; cb += 8) {
            // prefetch next batch before consuming current
            #pragma unroll
            for (int j = 0; j < 8; j++)
                xn[j] = __ldg(xa + (size_t)(cb + 8 + j) * HW);
            #pragma unroll
            for (int j = 0; j < 8; j++) {
                unsigned long long xd = pk2(xc[j], xc[j]);
                const ulonglong2* wr = (const ulonglong2*)(wsel + (cb + j) * 16);
                ulonglong2 a0 = wr[0];
                acc[0] = ffma2(xd, a0.x, acc[0]);
                acc[1] = ffma2(xd, a0.y, acc[1]);
                ulonglong2 a1 = wr[1];
                acc[2] = ffma2(xd, a1.x, acc[2]);
                acc[3] = ffma2(xd, a1.y, acc[3]);
                ulonglong2 a2 = wr[2];
                acc[4] = ffma2(xd, a2.x, acc[4]);
                acc[5] = ffma2(xd, a2.y, acc[5]);
                ulonglong2 a3 = wr[3];
                acc[6] = ffma2(xd, a3.x, acc[6]);
                acc[7] = ffma2(xd, a3.y, acc[7]);
            }
            #pragma unroll
            for (int j = 0; j < 8; j++) xc[j] = xn[j];
        }
        // final batch (c = 120..127)
        #pragma unroll
        for (int j = 0; j < 8; j++) {
            unsigned long long xd = pk2(xc[j], xc[j]);
            const ulonglong2* wr = (const ulonglong2*)(wsel + (120 + j) * 16);
            ulonglong2 a0 = wr[0];
            acc[0] = ffma2(xd, a0.x, acc[0]);
            acc[1] = ffma2(xd, a0.y, acc[1]);
            ulonglong2 a1 = wr[1];
            acc[2] = ffma2(xd, a1.x, acc[2]);
            acc[3] = ffma2(xd, a1.y, acc[3]);
            ulonglong2 a2 = wr[2];
            acc[4] = ffma2(xd, a2.x, acc[4]);
            acc[5] = ffma2(xd, a2.y, acc[5]);
            ulonglong2 a3 = wr[3];
            acc[6] = ffma2(xd, a3.x, acc[6]);
            acc[7] = ffma2(xd, a3.y, acc[7]);
        }

        float* dst = prj ? vs : fs;
        const float* bsel = prj ? vbs : fbs;
        #pragma unroll
        for (int j = 0; j < 8; j++) {
            float2 v = upk(acc[j]);
            dst[(2*j)   * FSTR + px] = v.x + bsel[2*j];
            dst[(2*j+1) * FSTR + px] = v.y + bsel[2*j+1];
        }
    }
    __syncthreads();

    // ---- Stage B: fp32 pooling (centers cf32, value centers vc) ----
    for (int it = t; it < 1568; it += NTHR) {
        int half = it >= 784;
        int rem = half ? it - 784 : it;
        int m = rem >> 4, cc = rem & 15;
        int i = m / 7, jj = m - i * 7;
        const float* src = half ? vs : fs;
        float ssum = 0.f;
        for (int r = SEG_S[i]; r < SEG_E[i]; r++)
            for (int q = SEG_S[jj]; q < SEG_E[jj]; q++)
                ssum += src[cc * FSTR + r * 16 + q];
        ssum *= SEG_I[i] * SEG_I[jj];
        if (half) vc[rem] = ssum; else cf32[rem] = ssum;
    }
    __syncthreads();

    if (t < 49) {
        float ss = 0.f;
        #pragma unroll
        for (int cc = 0; cc < 16; cc++) {
            float v = cf32[t*16+cc];
            ss = __fmaf_rn(v, v, ss);
        }
        float inv = 1.f / fmaxf(sqrtf(ss), 1e-12f);
        #pragma unroll
        for (int cc = 0; cc < 16; cc++) cf32[t*16+cc] *= inv;
    }
    __syncthreads();

    // ---- Stage C: ALL 512 threads; each covers half the clusters for pixel px ----
    const float alphaf = __ldg(salpha);
    const float betaf  = __ldg(sbeta);
    float ffn[16];
    {
        float ss = 0.f;
        #pragma unroll
        for (int cc = 0; cc < 16; cc++) {
            float v = fs[cc * FSTR + px];
            ffn[cc] = v;
            ss = __fmaf_rn(v, v, ss);
        }
        float inv = 1.f / fmaxf(sqrtf(ss), 1e-12f);
        #pragma unroll
        for (int cc = 0; cc < 16; cc++) ffn[cc] *= inv;

        float z1h = -1e30f, z2h = -1e30f;
        int bmh = 0;
        const int mstart = prj ? 25 : 0;
        const int mend   = prj ? 49 : 25;
        for (int m = mstart; m < mend; m++) {
            const float4* cr = (const float4*)(cf32 + m * 16);
            float dot = 0.f;
            #pragma unroll
            for (int q = 0; q < 4; q++) {
                float4 w = cr[q];
                dot = __fmaf_rn(w.x, ffn[4*q+0], dot);
                dot = __fmaf_rn(w.y, ffn[4*q+1], dot);
                dot = __fmaf_rn(w.z, ffn[4*q+2], dot);
                dot = __fmaf_rn(w.w, ffn[4*q+3], dot);
            }
            float z = betaf + alphaf * dot;
            if (z > z1h) { z2h = z1h; z1h = z; bmh = m; }
            else if (z > z2h) { z2h = z; }
        }
        zb1[t] = z1h; zb2[t] = z2h; bmb[t] = bmh;
    }
    __syncthreads();

    // ---- merge halves (lower 256 threads own the decision) ----
    float z1 = 1e30f, z2 = 0.f;          // upper threads: gap huge -> no vote
    int bm = 0;
    float s = 0.f;
    if (t < 256) {
        float a1 = zb1[t],       a2 = zb2[t];       int abm = bmb[t];
        float b1 = zb1[t + 256], b2 = zb2[t + 256]; int bbm = bmb[t + 256];
        if (a1 >= b1) { z1 = a1; bm = abm; z2 = fmaxf(a2, b1); }
        else          { z1 = b1; bm = bbm; z2 = fmaxf(b2, a1); }
        s = 1.f / (1.f + expf(-z1));
    }

    // ---- per-CTA vote: exact fallback if any pixel too close to call ----
    if (__syncthreads_or((t < 256) && (z1 - z2) < 1e-4f)) {
        for (int i = t; i < 2048; i += NTHR) {
            int c = i >> 4, o = i & 15;
            fw2[i] = fw[o * CIN + c];
        }
        __syncthreads();

        unsigned long long fhi[8], flo[8];
        if (t < 256) {
            #pragma unroll
            for (int j = 0; j < 8; j++) { fhi[j] = pk2(OFFSET_F, OFFSET_F); flo[j] = 0ull; }
            const float* xf = x + (size_t)batch * COUT * HW
                                + (size_t)(gx * 16 + apr) * WIDTH + (gy * 16 + apc);
            #pragma unroll 4
            for (int c = 0; c < CIN; c++) {
                float x1 = __ldg(xf + (size_t)c * HW);
                unsigned long long x1d = pk2(x1, x1);
                const ulonglong2* wf = (const ulonglong2*)(fw2 + c * 16);
                #pragma unroll
                for (int j = 0; j < 4; j++) {
                    ulonglong2 a = wf[j];
                    dfacc2(fhi[2*j],   flo[2*j],   x1d, a.x);
                    dfacc2(fhi[2*j+1], flo[2*j+1], x1d, a.y);
                }
            }
        }
        __syncthreads();     // all fs readers done before fp64 overwrite
        if (t < 256) {
            #pragma unroll
            for (int j = 0; j < 8; j++) {
                float2 h = upk(fhi[j]), l = upk(flo[j]);
                fsd[(2*j)   * FSTR + t] =
                    ((double)__fadd_rn(h.x, -OFFSET_F) + (double)l.x) + (double)fbs[2*j];
                fsd[(2*j+1) * FSTR + t] =
                    ((double)__fadd_rn(h.y, -OFFSET_F) + (double)l.y) + (double)fbs[2*j+1];
            }
        }
        __syncthreads();

        for (int it = t; it < 784; it += NTHR) {
            int m = it >> 4, cc = it & 15;
            int i = m / 7, jj = m - i * 7;
            double ssum = 0.0;
            for (int r = SEG_S[i]; r < SEG_E[i]; r++)
                for (int q = SEG_S[jj]; q < SEG_E[jj]; q++)
                    ssum += fsd[cc * FSTR + r * 16 + q];
            cfd[it] = ssum * (double)SEG_I[i] * (double)SEG_I[jj];
        }
        __syncthreads();
        if (t < 49) {
            double ss = 0.0;
            #pragma unroll
            for (int cc = 0; cc < 16; cc++) { double v = cfd[t*16+cc]; ss = fma(v, v, ss); }
            double inv = 1.0 / fmax(sqrt(ss), 1e-12);
            #pragma unroll
            for (int cc = 0; cc < 16; cc++) cfd[t*16+cc] *= inv;
        }
        __syncthreads();

        if (t < 256) {
            double invf;
            {
                double ss = 0.0;
                #pragma unroll
                for (int cc = 0; cc < 16; cc++) {
                    double v = fsd[cc * FSTR + t];
                    ss = fma(v, v, ss);
                }
                invf = 1.0 / fmax(sqrt(ss), 1e-12);
            }
            const double alpha = (double)alphaf;
            const double beta  = (double)betaf;

            float mx32 = -1e30f;
            for (int m = 0; m < 49; m++) {
                const float4* cr = (const float4*)(cf32 + m * 16);
                float dot = 0.f;
                #pragma unroll
                for (int q = 0; q < 4; q++) {
                    float4 w = cr[q];
                    dot = __fmaf_rn(w.x, ffn[4*q+0], dot);
                    dot = __fmaf_rn(w.y, ffn[4*q+1], dot);
                    dot = __fmaf_rn(w.z, ffn[4*q+2], dot);
                    dot = __fmaf_rn(w.w, ffn[4*q+3], dot);
                }
                mx32 = fmaxf(mx32, dot);
            }
            const float thr = mx32 - 1e-4f;
            double dz1 = -1e300, dz2 = -1e300, dz3 = -1e300;
            int m1 = 0, m2 = 0, m3 = 0;
            for (int m = 0; m < 49; m++) {
                const float4* cr = (const float4*)(cf32 + m * 16);
                float dot = 0.f;
                #pragma unroll
                for (int q = 0; q < 4; q++) {
                    float4 w = cr[q];
                    dot = __fmaf_rn(w.x, ffn[4*q+0], dot);
                    dot = __fmaf_rn(w.y, ffn[4*q+1], dot);
                    dot = __fmaf_rn(w.z, ffn[4*q+2], dot);
                    dot = __fmaf_rn(w.w, ffn[4*q+3], dot);
                }
                if (dot >= thr) {
                    double dd = 0.0;
                    #pragma unroll
                    for (int cc = 0; cc < 16; cc++)
                        dd = fma(cfd[m*16+cc], fsd[cc * FSTR + t], dd);
                    double z = beta + alpha * (dd * invf);
                    if (z > dz1)      { dz3 = dz2; m3 = m2; dz2 = dz1; m2 = m1; dz1 = z; m1 = m; }
                    else if (z > dz2) { dz3 = dz2; m3 = m2; dz2 = z;  m2 = m; }
                    else if (z > dz3) { dz3 = z;  m3 = m; }
                }
            }
            float s1f = (float)(1.0 / (1.0 + exp(-dz1)));
            bm = m1;
            if (dz1 - dz2 < 1e-5) {
                float s2f = (float)(1.0 / (1.0 + exp(-dz2)));
                if (s2f == s1f && m2 < bm) bm = m2;
                if (dz1 - dz3 < 1e-5) {
                    float s3f = (float)(1.0 / (1.0 + exp(-dz3)));
                    if (s3f == s1f && m3 < bm) bm = m3;
                }
            }
            s = s1f;
        }
        __syncthreads();
    }

    // ---- share (s, bm) so both halves can split the atomic work ----
    if (t < 256) { zb1[t] = s; bmb[t] = bm; }
    __syncthreads();

    // ---- aggregate: lower does agd + cc 0-7, upper does cc 8-15 (reads vs) ----
    {
        float sv = zb1[px];
        int bmv = bmb[px];
        if (t < 256) atomicAdd(&agd[bmv], sv);
        const int cc0 = prj ? 8 : 0;
        #pragma unroll
        for (int cc = 0; cc < 8; cc++)
            atomicAdd(&agn[bmv * 16 + cc0 + cc], sv * vs[(cc0 + cc) * FSTR + px]);
    }
    __syncthreads();

    // ---- merge agg  +  load p weights into the (now dead) vs region ----
    for (int it = t; it < 784; it += NTHR) {
        int m = it >> 4;
        agn[it] = (agn[it] + vc[it]) / (agd[m] + 1.f);
    }
    for (int i = t; i < 1024; i += NTHR)
        ((float4*)pwt2)[i] = ((const float4*)pw)[i];
    __syncthreads();

    // ---- write midT[n][cc] (transposed; fs region is dead now) ----
    if (t < 256) {
        #pragma unroll
        for (int q = 0; q < 8; q++) {
            float a = s * agn[bm * 16 + 2*q];
            float c = s * agn[bm * 16 + 2*q + 1];
            *(unsigned long long*)(midT + t * MSTR + 2*q) = pk2(a, c);
        }
    }
    __syncthreads();

    // ---- Stage D: thread = (o-group of 64) x (pixel pair); GEMM from regs ----
    {
        const int nid = t & 127, oid = t >> 7;
        const int n0 = 2 * nid;
        unsigned long long midA[8], midB[8];
        #pragma unroll
        for (int q = 0; q < 8; q++) {
            midA[q] = *(const unsigned long long*)(midT + n0 * MSTR + 2*q);
            midB[q] = *(const unsigned long long*)(midT + (n0 + 1) * MSTR + 2*q);
        }
        float* yb = out + (size_t)batch * COUT * HW
                        + (size_t)(gx * 16 + (n0 >> 4)) * WIDTH + (gy * 16 + (n0 & 15));
        const int obase = oid << 6;
        #pragma unroll 4
        for (int i = 0; i < 64; i++) {
            const int o = obase + i;
            const ulonglong2* wr = (const ulonglong2*)(pwt2 + o * 16);
            unsigned long long aA = 0ull, aB = 0ull;
            #pragma unroll
            for (int q = 0; q < 2; q++) {
                ulonglong2 w = wr[q];
                aA = ffma2(w.x, midA[2*q],   aA);
                aA = ffma2(w.y, midA[2*q+1], aA);
                aB = ffma2(w.x, midB[2*q],   aB);
                aB = ffma2(w.y, midB[2*q+1], aB);
            }
            #pragma unroll
            for (int q = 2; q < 4; q++) {
                ulonglong2 w = wr[q];
                aA = ffma2(w.x, midA[2*q],   aA);
                aA = ffma2(w.y, midA[2*q+1], aA);
                aB = ffma2(w.x, midB[2*q],   aB);
                aB = ffma2(w.y, midB[2*q+1], aB);
            }
            float2 fa = upk(aA), fbv = upk(aB);
            float pbo = pbs[o];
            float2 r;
            r.x = pbo + fa.x + fa.y;
            r.y = pbo + fbv.x + fbv.y;
            *(float2*)(yb + (size_t)o * HW) = r;
        }
    }
}

extern "C" void kernel_launch(void* const* d_in, const int* in_sizes, int n_in,
                              void* d_out, int out_size) {
    const float* x   = (const float*)d_in[0];
    const float* fw  = (const float*)d_in[1];
    const float* fb  = (const float*)d_in[2];
    const float* vw  = (const float*)d_in[3];
    const float* vb  = (const float*)d_in[4];
    const float* pw  = (const float*)d_in[5];
    const float* pb  = (const float*)d_in[6];
    const float* sa  = (const float*)d_in[7];
    const float* sb  = (const float*)d_in[8];
    float* out = (float*)d_out;

    cudaFuncSetAttribute(lc_kernel, cudaFuncAttributeMaxDynamicSharedMemorySize,
                         SMEM_BYTES);
    lc_kernel<<<NBLK, NTHR, SMEM_BYTES>>>(x, fw, fb, vw, vb, pw, pb, sa, sb, out);
}

// round 14
// speedup vs baseline: 1.5895x; 1.0370x over previous
#include <cuda_runtime.h>
#include <math.h>

// Problem constants
#define CIN    128
#define CMID   16
#define COUT   256
#define HW     12544
#define WIDTH  112
#define NBLK   784
#define NTHR   512

// Pooling segments 16 -> 7 (overlapping avg pool)
__constant__ int   SEG_S[7] = {0, 2, 4, 6, 9, 11, 13};
__constant__ int   SEG_E[7] = {3, 5, 7, 10, 12, 14, 16};
__constant__ float SEG_I[7] = {1.f/3.f, 1.f/3.f, 1.f/3.f, 0.25f, 1.f/3.f, 1.f/3.f, 1.f/3.f};

// Inter-kernel scratch (static device allocations — allowed)
__device__ float g_agg[NBLK * 784];   // merged agg per block  [49][16]
__device__ float g_sv [NBLK * 256];   // per-pixel sigmoid
__device__ int   g_bm [NBLK * 256];   // per-pixel argmax cluster

// ---- packed f32x2 helpers (sm_103a, PTX-only) ----
__device__ __forceinline__ unsigned long long pk2(float a, float b) {
    unsigned long long r;
    asm("mov.b64 %0, {%1, %2};" : "=l"(r) : "f"(a), "f"(b));
    return r;
}
__device__ __forceinline__ unsigned long long ffma2(unsigned long long a,
                                                    unsigned long long b,
                                                    unsigned long long c) {
    unsigned long long d;
    asm("fma.rn.f32x2 %0, %1, %2, %3;" : "=l"(d) : "l"(a), "l"(b), "l"(c));
    return d;
}
__device__ __forceinline__ unsigned long long fmul2(unsigned long long a,
                                                    unsigned long long b) {
    unsigned long long d;
    asm("mul.rn.f32x2 %0, %1, %2;" : "=l"(d) : "l"(a), "l"(b));
    return d;
}
__device__ __forceinline__ unsigned long long fadd2(unsigned long long a,
                                                    unsigned long long b) {
    unsigned long long d;
    asm("add.rn.f32x2 %0, %1, %2;" : "=l"(d) : "l"(a), "l"(b));
    return d;
}
__device__ __forceinline__ float2 upk(unsigned long long v) {
    float2 f;
    asm("mov.b64 {%0, %1}, %2;" : "=f"(f.x), "=f"(f.y) : "l"(v));
    return f;
}

#define SGNMASK 0x8000000080000000ULL
#define OFFSET_F 16384.0f

// Exact compensated accumulate (fallback path only).
__device__ __forceinline__ void dfacc2(unsigned long long& hi, unsigned long long& lo,
                                       unsigned long long xd, unsigned long long w) {
    unsigned long long ph = fmul2(xd, w);
    unsigned long long pl = ffma2(xd, w, ph ^ SGNMASK);
    unsigned long long s  = fadd2(hi, ph);
    unsigned long long d  = fadd2(hi, s ^ SGNMASK);
    unsigned long long e  = fadd2(d, ph);
    lo = fadd2(lo, fadd2(e, pl));
    hi = s;
}

// ---- Kernel 1 shared memory layout ----
#define FSTR 257     // stride (floats for fs/vs, doubles for fsd)
#define OFF_R0    0                          // union: fs float[16*257] (common)
                                             //        fsd double[16*257] (fallback)
#define OFF_CFD   (OFF_R0 + 16*FSTR*8)       // double[784] exact centers (fallback)
#define OFF_WBUF  (OFF_CFD + 784*8)          // float[4096] time-shared:
                                             //  A: wsf[0:2048] wsv[2048:4096]
                                             //  B/C: vc[0:784] cf32[784:1568]
                                             //  fallback: fw2[1568:3616]
#define OFF_VS    (OFF_WBUF + 4096*4)        // float[16*257] v features
#define OFF_AGN   (OFF_VS  + 16*FSTR*4)      // float[784]
#define OFF_AGD   (OFF_AGN + 784*4)          // float[52]
#define OFF_FBS   (OFF_AGD + 52*4)           // float[16]
#define OFF_VBS   (OFF_FBS + 16*4)           // float[16]
#define OFF_ZB1   (OFF_VBS + 16*4)           // float[512] half top-1 z (later: s)
#define OFF_ZB2   (OFF_ZB1 + 512*4)          // float[512] half top-2 z
#define OFF_BMB   (OFF_ZB2 + 512*4)          // int[512]   half argmax
#define SMEM1_BYTES (OFF_BMB + 512*4)        // 81,616 B -> 2 CTAs/SM @512thr

extern "C" __global__ void __launch_bounds__(NTHR, 2)
lc_k1(const float* __restrict__ x,   const float* __restrict__ fw,
      const float* __restrict__ fb,  const float* __restrict__ vw,
      const float* __restrict__ vb,  const float* __restrict__ salpha,
      const float* __restrict__ sbeta)
{
    extern __shared__ char smraw[];
    float*  fs   = (float*)(smraw + OFF_R0);
    double* fsd  = (double*)(smraw + OFF_R0);
    double* cfd  = (double*)(smraw + OFF_CFD);
    float*  wbuf = (float*)(smraw + OFF_WBUF);
    float*  vs   = (float*)(smraw + OFF_VS);
    float*  agn  = (float*)(smraw + OFF_AGN);
    float*  agd  = (float*)(smraw + OFF_AGD);
    float*  fbs  = (float*)(smraw + OFF_FBS);
    float*  vbs  = (float*)(smraw + OFF_VBS);
    float*  zb1  = (float*)(smraw + OFF_ZB1);
    float*  zb2  = (float*)(smraw + OFF_ZB2);
    int*    bmb  = (int*)(smraw + OFF_BMB);
    float*  wsf  = wbuf;
    float*  wsv  = wbuf + 2048;
    float*  vc   = wbuf;
    float*  cf32 = wbuf + 784;
    float*  fw2  = wbuf + 1568;

    const int t = threadIdx.x;
    const int b = blockIdx.x;
    const int batch = b / 49;
    const int g = b - batch * 49;
    const int gx = g / 7, gy = g - (g / 7) * 7;

    // ---- stage A weights + biases into smem ----
    for (int i = t; i < 2048; i += NTHR) {
        int c = i >> 4, o = i & 15;
        wsf[i] = fw[o * CIN + c];
        wsv[i] = vw[o * CIN + c];
    }
    if (t < 16) { fbs[t] = fb[t]; vbs[t] = vb[t]; }
    for (int i = t; i < 784; i += NTHR) agn[i] = 0.f;
    if (t < 49) agd[t] = 0.f;
    __syncthreads();

    // ---- Stage A: warps 0-7 -> f, warps 8-15 -> v (1 pixel, 128 ch each) ----
    const int px  = t & 255;             // pixel
    const int prj = t >> 8;              // 0 = f, 1 = v
    const int apr = px >> 4, apc = px & 15;
    const float* xa = x + (size_t)batch * COUT * HW + (size_t)prj * CIN * HW
                        + (size_t)(gx * 16 + apr) * WIDTH + (gy * 16 + apc);
    const float* wsel = prj ? wsv : wsf;
    {
        unsigned long long acc[8];
        #pragma unroll
        for (int j = 0; j < 8; j++) acc[j] = 0ull;
        #pragma unroll 8
        for (int c = 0; c < CIN; c++) {
            float xv = __ldg(xa + (size_t)c * HW);
            unsigned long long xd = pk2(xv, xv);
            const ulonglong2* wr = (const ulonglong2*)(wsel + c * 16);
            #pragma unroll
            for (int j = 0; j < 4; j++) {
                ulonglong2 a = wr[j];
                acc[2*j]   = ffma2(xd, a.x, acc[2*j]);
                acc[2*j+1] = ffma2(xd, a.y, acc[2*j+1]);
            }
        }
        float* dst = prj ? vs : fs;
        const float* bsel = prj ? vbs : fbs;
        #pragma unroll
        for (int j = 0; j < 8; j++) {
            float2 v = upk(acc[j]);
            dst[(2*j)   * FSTR + px] = v.x + bsel[2*j];
            dst[(2*j+1) * FSTR + px] = v.y + bsel[2*j+1];
        }
    }
    __syncthreads();

    // ---- Stage B: fp32 pooling (centers cf32, value centers vc) ----
    for (int it = t; it < 1568; it += NTHR) {
        int half = it >= 784;
        int rem = half ? it - 784 : it;
        int m = rem >> 4, cc = rem & 15;
        int i = m / 7, jj = m - i * 7;
        const float* src = half ? vs : fs;
        float ssum = 0.f;
        for (int r = SEG_S[i]; r < SEG_E[i]; r++)
            for (int q = SEG_S[jj]; q < SEG_E[jj]; q++)
                ssum += src[cc * FSTR + r * 16 + q];
        ssum *= SEG_I[i] * SEG_I[jj];
        if (half) vc[rem] = ssum; else cf32[rem] = ssum;
    }
    __syncthreads();

    if (t < 49) {
        float ss = 0.f;
        #pragma unroll
        for (int cc = 0; cc < 16; cc++) {
            float v = cf32[t*16+cc];
            ss = __fmaf_rn(v, v, ss);
        }
        float inv = 1.f / fmaxf(sqrtf(ss), 1e-12f);
        #pragma unroll
        for (int cc = 0; cc < 16; cc++) cf32[t*16+cc] *= inv;
    }
    __syncthreads();

    // ---- Stage C: ALL 512 threads; each covers half the clusters for pixel px ----
    const float alphaf = __ldg(salpha);
    const float betaf  = __ldg(sbeta);
    float ffn[16];
    {
        float ss = 0.f;
        #pragma unroll
        for (int cc = 0; cc < 16; cc++) {
            float v = fs[cc * FSTR + px];
            ffn[cc] = v;
            ss = __fmaf_rn(v, v, ss);
        }
        float inv = 1.f / fmaxf(sqrtf(ss), 1e-12f);
        #pragma unroll
        for (int cc = 0; cc < 16; cc++) ffn[cc] *= inv;

        float z1h = -1e30f, z2h = -1e30f;
        int bmh = 0;
        const int mstart = prj ? 25 : 0;
        const int mend   = prj ? 49 : 25;
        for (int m = mstart; m < mend; m++) {
            const float4* cr = (const float4*)(cf32 + m * 16);
            float dot = 0.f;
            #pragma unroll
            for (int q = 0; q < 4; q++) {
                float4 w = cr[q];
                dot = __fmaf_rn(w.x, ffn[4*q+0], dot);
                dot = __fmaf_rn(w.y, ffn[4*q+1], dot);
                dot = __fmaf_rn(w.z, ffn[4*q+2], dot);
                dot = __fmaf_rn(w.w, ffn[4*q+3], dot);
            }
            float z = betaf + alphaf * dot;
            if (z > z1h) { z2h = z1h; z1h = z; bmh = m; }
            else if (z > z2h) { z2h = z; }
        }
        zb1[t] = z1h; zb2[t] = z2h; bmb[t] = bmh;
    }
    __syncthreads();

    // ---- merge halves (lower 256 threads own the decision) ----
    float z1 = 1e30f, z2 = 0.f;          // upper threads: gap huge -> no vote
    int bm = 0;
    float s = 0.f;
    if (t < 256) {
        float a1 = zb1[t],       a2 = zb2[t];       int abm = bmb[t];
        float b1 = zb1[t + 256], b2 = zb2[t + 256]; int bbm = bmb[t + 256];
        if (a1 >= b1) { z1 = a1; bm = abm; z2 = fmaxf(a2, b1); }
        else          { z1 = b1; bm = bbm; z2 = fmaxf(b2, a1); }
        s = 1.f / (1.f + expf(-z1));
    }

    // ---- per-CTA vote: exact fallback if any pixel too close to call ----
    if (__syncthreads_or((t < 256) && (z1 - z2) < 1e-4f)) {
        for (int i = t; i < 2048; i += NTHR) {
            int c = i >> 4, o = i & 15;
            fw2[i] = fw[o * CIN + c];
        }
        __syncthreads();

        unsigned long long fhi[8], flo[8];
        if (t < 256) {
            #pragma unroll
            for (int j = 0; j < 8; j++) { fhi[j] = pk2(OFFSET_F, OFFSET_F); flo[j] = 0ull; }
            const float* xf = x + (size_t)batch * COUT * HW
                                + (size_t)(gx * 16 + apr) * WIDTH + (gy * 16 + apc);
            #pragma unroll 4
            for (int c = 0; c < CIN; c++) {
                float x1 = __ldg(xf + (size_t)c * HW);
                unsigned long long x1d = pk2(x1, x1);
                const ulonglong2* wf = (const ulonglong2*)(fw2 + c * 16);
                #pragma unroll
                for (int j = 0; j < 4; j++) {
                    ulonglong2 a = wf[j];
                    dfacc2(fhi[2*j],   flo[2*j],   x1d, a.x);
                    dfacc2(fhi[2*j+1], flo[2*j+1], x1d, a.y);
                }
            }
        }
        __syncthreads();     // all fs readers done before fp64 overwrite
        if (t < 256) {
            #pragma unroll
            for (int j = 0; j < 8; j++) {
                float2 h = upk(fhi[j]), l = upk(flo[j]);
                fsd[(2*j)   * FSTR + t] =
                    ((double)__fadd_rn(h.x, -OFFSET_F) + (double)l.x) + (double)fbs[2*j];
                fsd[(2*j+1) * FSTR + t] =
                    ((double)__fadd_rn(h.y, -OFFSET_F) + (double)l.y) + (double)fbs[2*j+1];
            }
        }
        __syncthreads();

        for (int it = t; it < 784; it += NTHR) {
            int m = it >> 4, cc = it & 15;
            int i = m / 7, jj = m - i * 7;
            double ssum = 0.0;
            for (int r = SEG_S[i]; r < SEG_E[i]; r++)
                for (int q = SEG_S[jj]; q < SEG_E[jj]; q++)
                    ssum += fsd[cc * FSTR + r * 16 + q];
            cfd[it] = ssum * (double)SEG_I[i] * (double)SEG_I[jj];
        }
        __syncthreads();
        if (t < 49) {
            double ss = 0.0;
            #pragma unroll
            for (int cc = 0; cc < 16; cc++) { double v = cfd[t*16+cc]; ss = fma(v, v, ss); }
            double inv = 1.0 / fmax(sqrt(ss), 1e-12);
            #pragma unroll
            for (int cc = 0; cc < 16; cc++) cfd[t*16+cc] *= inv;
        }
        __syncthreads();

        if (t < 256) {
            double invf;
            {
                double ss = 0.0;
                #pragma unroll
                for (int cc = 0; cc < 16; cc++) {
                    double v = fsd[cc * FSTR + t];
                    ss = fma(v, v, ss);
                }
                invf = 1.0 / fmax(sqrt(ss), 1e-12);
            }
            const double alpha = (double)alphaf;
            const double beta  = (double)betaf;

            float mx32 = -1e30f;
            for (int m = 0; m < 49; m++) {
                const float4* cr = (const float4*)(cf32 + m * 16);
                float dot = 0.f;
                #pragma unroll
                for (int q = 0; q < 4; q++) {
                    float4 w = cr[q];
                    dot = __fmaf_rn(w.x, ffn[4*q+0], dot);
                    dot = __fmaf_rn(w.y, ffn[4*q+1], dot);
                    dot = __fmaf_rn(w.z, ffn[4*q+2], dot);
                    dot = __fmaf_rn(w.w, ffn[4*q+3], dot);
                }
                mx32 = fmaxf(mx32, dot);
            }
            const float thr = mx32 - 1e-4f;
            double dz1 = -1e300, dz2 = -1e300, dz3 = -1e300;
            int m1 = 0, m2 = 0, m3 = 0;
            for (int m = 0; m < 49; m++) {
                const float4* cr = (const float4*)(cf32 + m * 16);
                float dot = 0.f;
                #pragma unroll
                for (int q = 0; q < 4; q++) {
                    float4 w = cr[q];
                    dot = __fmaf_rn(w.x, ffn[4*q+0], dot);
                    dot = __fmaf_rn(w.y, ffn[4*q+1], dot);
                    dot = __fmaf_rn(w.z, ffn[4*q+2], dot);
                    dot = __fmaf_rn(w.w, ffn[4*q+3], dot);
                }
                if (dot >= thr) {
                    double dd = 0.0;
                    #pragma unroll
                    for (int cc = 0; cc < 16; cc++)
                        dd = fma(cfd[m*16+cc], fsd[cc * FSTR + t], dd);
                    double z = beta + alpha * (dd * invf);
                    if (z > dz1)      { dz3 = dz2; m3 = m2; dz2 = dz1; m2 = m1; dz1 = z; m1 = m; }
                    else if (z > dz2) { dz3 = dz2; m3 = m2; dz2 = z;  m2 = m; }
                    else if (z > dz3) { dz3 = z;  m3 = m; }
                }
            }
            float s1f = (float)(1.0 / (1.0 + exp(-dz1)));
            bm = m1;
            if (dz1 - dz2 < 1e-5) {
                float s2f = (float)(1.0 / (1.0 + exp(-dz2)));
                if (s2f == s1f && m2 < bm) bm = m2;
                if (dz1 - dz3 < 1e-5) {
                    float s3f = (float)(1.0 / (1.0 + exp(-dz3)));
                    if (s3f == s1f && m3 < bm) bm = m3;
                }
            }
            s = s1f;
        }
        __syncthreads();
    }

    // ---- share (s, bm) so both halves can split the atomic work ----
    if (t < 256) { zb1[t] = s; bmb[t] = bm; }
    __syncthreads();

    // ---- aggregate: lower does agd + cc 0-7, upper does cc 8-15 (reads vs) ----
    {
        float sv = zb1[px];
        int bmv = bmb[px];
        if (t < 256) atomicAdd(&agd[bmv], sv);
        const int cc0 = prj ? 8 : 0;
        #pragma unroll
        for (int cc = 0; cc < 8; cc++)
            atomicAdd(&agn[bmv * 16 + cc0 + cc], sv * vs[(cc0 + cc) * FSTR + px]);
    }
    __syncthreads();

    // ---- merge agg directly to global scratch; write (s, bm) ----
    for (int it = t; it < 784; it += NTHR) {
        int m = it >> 4;
        g_agg[(size_t)b * 784 + it] = (agn[it] + vc[it]) / (agd[m] + 1.f);
    }
    if (t < 256) {
        g_sv[b * 256 + t] = s;
        g_bm[b * 256 + t] = bm;
    }
}

// ---- Kernel 2: P = agg @ pw^T per block; y[o][n] = s_n * P[bm_n][o] + pb[o] ----
#define PSTR 261    // P row stride: 261 % 32 = 5, spreads cluster rows over banks
#define K2_OFF_P    0                            // float[49*261] = 51,156 B
#define K2_OFF_AGG  ((K2_OFF_P + 49*PSTR*4 + 15) & ~15)   // float[784], 16B-aligned
#define K2_OFF_SV   ((K2_OFF_AGG + 784*4 + 15) & ~15)     // float[256]
#define K2_OFF_BM   ((K2_OFF_SV + 256*4 + 15) & ~15)      // int[256]
#define K2_OFF_PBS  ((K2_OFF_BM + 256*4 + 15) & ~15)      // float[256]
#define SMEM2_BYTES (K2_OFF_PBS + 256*4)

extern "C" __global__ void __launch_bounds__(NTHR, 2)
lc_k2(const float* __restrict__ pw, const float* __restrict__ pbg,
      float* __restrict__ out)
{
    extern __shared__ char smraw[];
    float* Pm  = (float*)(smraw + K2_OFF_P);
    float* agg = (float*)(smraw + K2_OFF_AGG);
    float* sv  = (float*)(smraw + K2_OFF_SV);
    int*   bmv = (int*)(smraw + K2_OFF_BM);
    float* pbs = (float*)(smraw + K2_OFF_PBS);

    const int t = threadIdx.x;
    const int b = blockIdx.x;
    const int batch = b / 49;
    const int g = b - batch * 49;
    const int gx = g / 7, gy = g - (g / 7) * 7;

    for (int i = t; i < 784; i += NTHR) agg[i] = g_agg[(size_t)b * 784 + i];
    if (t < 256) {
        sv[t]  = g_sv[b * 256 + t];
        bmv[t] = g_bm[b * 256 + t];
        pbs[t] = pbg[t];
    }
    __syncthreads();

    // P-GEMM: thread = (o, m-half). pw row held in registers; agg broadcast LDS.
    {
        const int o = t & 255, mh = t >> 8;
        const float4* wrow = (const float4*)(pw + o * 16);
        float4 w0 = __ldg(wrow), w1 = __ldg(wrow + 1);
        float4 w2 = __ldg(wrow + 2), w3 = __ldg(wrow + 3);
        const int m0 = mh ? 25 : 0, m1 = mh ? 49 : 25;
        for (int m = m0; m < m1; m++) {
            const float4* ar = (const float4*)(agg + m * 16);
            float4 a0 = ar[0], a1 = ar[1], a2 = ar[2], a3 = ar[3];
            float dot = 0.f;
            dot = __fmaf_rn(w0.x, a0.x, dot); dot = __fmaf_rn(w0.y, a0.y, dot);
            dot = __fmaf_rn(w0.z, a0.z, dot); dot = __fmaf_rn(w0.w, a0.w, dot);
            dot = __fmaf_rn(w1.x, a1.x, dot); dot = __fmaf_rn(w1.y, a1.y, dot);
            dot = __fmaf_rn(w1.z, a1.z, dot); dot = __fmaf_rn(w1.w, a1.w, dot);
            dot = __fmaf_rn(w2.x, a2.x, dot); dot = __fmaf_rn(w2.y, a2.y, dot);
            dot = __fmaf_rn(w2.z, a2.z, dot); dot = __fmaf_rn(w2.w, a2.w, dot);
            dot = __fmaf_rn(w3.x, a3.x, dot); dot = __fmaf_rn(w3.y, a3.y, dot);
            dot = __fmaf_rn(w3.z, a3.z, dot); dot = __fmaf_rn(w3.w, a3.w, dot);
            Pm[m * PSTR + o] = dot;
        }
    }
    __syncthreads();

    // Epilogue: thread = (o-group of 64) x (pixel pair); coalesced STG.64
    {
        const int nid = t & 127, oid = t >> 7;
        const int n0 = 2 * nid;
        const float s0 = sv[n0], s1 = sv[n0 + 1];
        const float* P0 = Pm + bmv[n0] * PSTR;
        const float* P1 = Pm + bmv[n0 + 1] * PSTR;
        float* yb = out + (size_t)batch * COUT * HW
                        + (size_t)(gx * 16 + (n0 >> 4)) * WIDTH + (gy * 16 + (n0 & 15));
        const int obase = oid << 6;
        #pragma unroll 8
        for (int i = 0; i < 64; i++) {
            const int o = obase + i;
            float pbv = pbs[o];
            float2 r;
            r.x = __fmaf_rn(s0, P0[o], pbv);
            r.y = __fmaf_rn(s1, P1[o], pbv);
            *(float2*)(yb + (size_t)o * HW) = r;
        }
    }
}

extern "C" void kernel_launch(void* const* d_in, const int* in_sizes, int n_in,
                              void* d_out, int out_size) {
    const float* x   = (const float*)d_in[0];
    const float* fw  = (const float*)d_in[1];
    const float* fb  = (const float*)d_in[2];
    const float* vw  = (const float*)d_in[3];
    const float* vb  = (const float*)d_in[4];
    const float* pw  = (const float*)d_in[5];
    const float* pb  = (const float*)d_in[6];
    const float* sa  = (const float*)d_in[7];
    const float* sb  = (const float*)d_in[8];
    float* out = (float*)d_out;

    cudaFuncSetAttribute(lc_k1, cudaFuncAttributeMaxDynamicSharedMemorySize,
                         SMEM1_BYTES);
    cudaFuncSetAttribute(lc_k2, cudaFuncAttributeMaxDynamicSharedMemorySize,
                         SMEM2_BYTES);
    lc_k1<<<NBLK, NTHR, SMEM1_BYTES>>>(x, fw, fb, vw, vb, sa, sb);
    lc_k2<<<NBLK, NTHR, SMEM2_BYTES>>>(pw, pb, out);
}

// round 15
// speedup vs baseline: 1.5961x; 1.0042x over previous
#include <cuda_runtime.h>
#include <math.h>

// Problem constants
#define CIN    128
#define CMID   16
#define COUT   256
#define HW     12544
#define WIDTH  112
#define NBLK   784
#define NTHR   512

// Pooling segments 16 -> 7 (overlapping avg pool)
__constant__ int   SEG_S[7] = {0, 2, 4, 6, 9, 11, 13};
__constant__ int   SEG_E[7] = {3, 5, 7, 10, 12, 14, 16};
__constant__ float SEG_I[7] = {1.f/3.f, 1.f/3.f, 1.f/3.f, 0.25f, 1.f/3.f, 1.f/3.f, 1.f/3.f};

// Inter-kernel scratch (static device allocations — allowed)
__device__ float g_agg[NBLK * 784];   // merged agg per block  [49][16]
__device__ float g_sv [NBLK * 256];   // per-pixel sigmoid
__device__ int   g_bm [NBLK * 256];   // per-pixel argmax cluster

// ---- packed f32x2 helpers (sm_103a, PTX-only) ----
__device__ __forceinline__ unsigned long long pk2(float a, float b) {
    unsigned long long r;
    asm("mov.b64 %0, {%1, %2};" : "=l"(r) : "f"(a), "f"(b));
    return r;
}
__device__ __forceinline__ unsigned long long ffma2(unsigned long long a,
                                                    unsigned long long b,
                                                    unsigned long long c) {
    unsigned long long d;
    asm("fma.rn.f32x2 %0, %1, %2, %3;" : "=l"(d) : "l"(a), "l"(b), "l"(c));
    return d;
}
__device__ __forceinline__ unsigned long long fmul2(unsigned long long a,
                                                    unsigned long long b) {
    unsigned long long d;
    asm("mul.rn.f32x2 %0, %1, %2;" : "=l"(d) : "l"(a), "l"(b));
    return d;
}
__device__ __forceinline__ unsigned long long fadd2(unsigned long long a,
                                                    unsigned long long b) {
    unsigned long long d;
    asm("add.rn.f32x2 %0, %1, %2;" : "=l"(d) : "l"(a), "l"(b));
    return d;
}
__device__ __forceinline__ float2 upk(unsigned long long v) {
    float2 f;
    asm("mov.b64 {%0, %1}, %2;" : "=f"(f.x), "=f"(f.y) : "l"(v));
    return f;
}

#define SGNMASK 0x8000000080000000ULL
#define OFFSET_F 16384.0f

// Exact compensated accumulate (fallback path only).
__device__ __forceinline__ void dfacc2(unsigned long long& hi, unsigned long long& lo,
                                       unsigned long long xd, unsigned long long w) {
    unsigned long long ph = fmul2(xd, w);
    unsigned long long pl = ffma2(xd, w, ph ^ SGNMASK);
    unsigned long long s  = fadd2(hi, ph);
    unsigned long long d  = fadd2(hi, s ^ SGNMASK);
    unsigned long long e  = fadd2(d, ph);
    lo = fadd2(lo, fadd2(e, pl));
    hi = s;
}

// ---- Kernel 1 shared memory layout ----
#define FSTR 257     // stride (floats for fs/vs, doubles for fsd)
#define OFF_R0    0                          // union: fs float[16*257] (common)
                                             //        fsd double[16*257] (fallback)
#define OFF_CFD   (OFF_R0 + 16*FSTR*8)       // double[784] exact centers (fallback)
#define OFF_WBUF  (OFF_CFD + 784*8)          // float[4096] time-shared:
                                             //  A: wsf[0:2048] wsv[2048:4096]
                                             //  B/C: vc[0:784] cf32[784:1568]
                                             //  fallback: fw2[1568:3616]
#define OFF_VS    (OFF_WBUF + 4096*4)        // float[16*257] v features
#define OFF_AGN   (OFF_VS  + 16*FSTR*4)      // float[784]
#define OFF_AGD   (OFF_AGN + 784*4)          // float[52]
#define OFF_FBS   (OFF_AGD + 52*4)           // float[16]
#define OFF_VBS   (OFF_FBS + 16*4)           // float[16]
#define OFF_ZB1   (OFF_VBS + 16*4)           // float[512] half top-1 z (later: s)
#define OFF_ZB2   (OFF_ZB1 + 512*4)          // float[512] half top-2 z
#define OFF_BMB   (OFF_ZB2 + 512*4)          // int[512]   half argmax
#define SMEM1_BYTES (OFF_BMB + 512*4)        // 81,616 B -> 2 CTAs/SM @512thr

extern "C" __global__ void __launch_bounds__(NTHR, 2)
lc_k1(const float* __restrict__ x,   const float* __restrict__ fw,
      const float* __restrict__ fb,  const float* __restrict__ vw,
      const float* __restrict__ vb,  const float* __restrict__ salpha,
      const float* __restrict__ sbeta)
{
    extern __shared__ char smraw[];
    float*  fs   = (float*)(smraw + OFF_R0);
    double* fsd  = (double*)(smraw + OFF_R0);
    double* cfd  = (double*)(smraw + OFF_CFD);
    float*  wbuf = (float*)(smraw + OFF_WBUF);
    float*  vs   = (float*)(smraw + OFF_VS);
    float*  agn  = (float*)(smraw + OFF_AGN);
    float*  agd  = (float*)(smraw + OFF_AGD);
    float*  fbs  = (float*)(smraw + OFF_FBS);
    float*  vbs  = (float*)(smraw + OFF_VBS);
    float*  zb1  = (float*)(smraw + OFF_ZB1);
    float*  zb2  = (float*)(smraw + OFF_ZB2);
    int*    bmb  = (int*)(smraw + OFF_BMB);
    float*  wsf  = wbuf;
    float*  wsv  = wbuf + 2048;
    float*  vc   = wbuf;
    float*  cf32 = wbuf + 784;
    float*  fw2  = wbuf + 1568;

    const int t = threadIdx.x;
    const int b = blockIdx.x;
    const int batch = b / 49;
    const int g = b - batch * 49;
    const int gx = g / 7, gy = g - (g / 7) * 7;

    // ---- stage A weights + biases into smem ----
    for (int i = t; i < 2048; i += NTHR) {
        int c = i >> 4, o = i & 15;
        wsf[i] = fw[o * CIN + c];
        wsv[i] = vw[o * CIN + c];
    }
    if (t < 16) { fbs[t] = fb[t]; vbs[t] = vb[t]; }
    for (int i = t; i < 784; i += NTHR) agn[i] = 0.f;
    if (t < 49) agd[t] = 0.f;
    __syncthreads();

    // ---- Stage A: thread = (pixel-pair, c-half, projection) ----
    // 2 W-adjacent pixels x 16 outputs x 64 channels per thread; LDG.64 x.
    const int px  = t & 255;             // pixel id for later stages
    const int prj = t >> 8;              // 0 = f, 1 = v (later stages)
    const int apr = px >> 4, apc = px & 15;   // fallback pointer base
    {
        const int pp   = t & 127;            // pixel pair 0..127
        const int half = (t >> 7) & 1;       // c-half
        const int aprj = t >> 8;             // projection
        const int pn0  = 2 * pp;             // even pixel (W-adjacent pair)
        const int ar   = pn0 >> 4, ac = pn0 & 15;
        const float* xa2 = x + (size_t)batch * COUT * HW + (size_t)aprj * CIN * HW
                             + (size_t)(gx * 16 + ar) * WIDTH + (gy * 16 + ac);
        const float* wsel = aprj ? wsv : wsf;
        const int c0 = half << 6;            // 0 or 64

        unsigned long long accA[8], accB[8];
        #pragma unroll
        for (int j = 0; j < 8; j++) { accA[j] = 0ull; accB[j] = 0ull; }

        #pragma unroll 4
        for (int ci = 0; ci < 64; ci++) {
            const int c = c0 + ci;
            float2 xv = __ldg((const float2*)(xa2 + (size_t)c * HW));
            unsigned long long xd0 = pk2(xv.x, xv.x);
            unsigned long long xd1 = pk2(xv.y, xv.y);
            const ulonglong2* wr = (const ulonglong2*)(wsel + c * 16);
            #pragma unroll
            for (int j = 0; j < 4; j++) {
                ulonglong2 a = wr[j];
                accA[2*j]   = ffma2(xd0, a.x, accA[2*j]);
                accA[2*j+1] = ffma2(xd0, a.y, accA[2*j+1]);
                accB[2*j]   = ffma2(xd1, a.x, accB[2*j]);
                accB[2*j+1] = ffma2(xd1, a.y, accB[2*j+1]);
            }
        }

        float* dst = aprj ? vs : fs;
        if (half) {
            // store raw partials for c = 64..127
            #pragma unroll
            for (int j = 0; j < 8; j++) {
                float2 a = upk(accA[j]), bb = upk(accB[j]);
                dst[(2*j)   * FSTR + pn0]     = a.x;
                dst[(2*j+1) * FSTR + pn0]     = a.y;
                dst[(2*j)   * FSTR + pn0 + 1] = bb.x;
                dst[(2*j+1) * FSTR + pn0 + 1] = bb.y;
            }
        }
        __syncthreads();
        if (!half) {
            const float* bsel = aprj ? vbs : fbs;
            #pragma unroll
            for (int j = 0; j < 8; j++) {
                float2 a = upk(accA[j]), bb = upk(accB[j]);
                float b0 = bsel[2*j], b1 = bsel[2*j+1];
                dst[(2*j)   * FSTR + pn0]     += a.x + b0;
                dst[(2*j+1) * FSTR + pn0]     += a.y + b1;
                dst[(2*j)   * FSTR + pn0 + 1] += bb.x + b0;
                dst[(2*j+1) * FSTR + pn0 + 1] += bb.y + b1;
            }
        }
    }
    __syncthreads();

    // ---- Stage B: fp32 pooling (centers cf32, value centers vc) ----
    for (int it = t; it < 1568; it += NTHR) {
        int half = it >= 784;
        int rem = half ? it - 784 : it;
        int m = rem >> 4, cc = rem & 15;
        int i = m / 7, jj = m - i * 7;
        const float* src = half ? vs : fs;
        float ssum = 0.f;
        for (int r = SEG_S[i]; r < SEG_E[i]; r++)
            for (int q = SEG_S[jj]; q < SEG_E[jj]; q++)
                ssum += src[cc * FSTR + r * 16 + q];
        ssum *= SEG_I[i] * SEG_I[jj];
        if (half) vc[rem] = ssum; else cf32[rem] = ssum;
    }
    __syncthreads();

    if (t < 49) {
        float ss = 0.f;
        #pragma unroll
        for (int cc = 0; cc < 16; cc++) {
            float v = cf32[t*16+cc];
            ss = __fmaf_rn(v, v, ss);
        }
        float inv = 1.f / fmaxf(sqrtf(ss), 1e-12f);
        #pragma unroll
        for (int cc = 0; cc < 16; cc++) cf32[t*16+cc] *= inv;
    }
    __syncthreads();

    // ---- Stage C: ALL 512 threads; each covers half the clusters for pixel px ----
    const float alphaf = __ldg(salpha);
    const float betaf  = __ldg(sbeta);
    float ffn[16];
    {
        float ss = 0.f;
        #pragma unroll
        for (int cc = 0; cc < 16; cc++) {
            float v = fs[cc * FSTR + px];
            ffn[cc] = v;
            ss = __fmaf_rn(v, v, ss);
        }
        float inv = 1.f / fmaxf(sqrtf(ss), 1e-12f);
        #pragma unroll
        for (int cc = 0; cc < 16; cc++) ffn[cc] *= inv;

        float z1h = -1e30f, z2h = -1e30f;
        int bmh = 0;
        const int mstart = prj ? 25 : 0;
        const int mend   = prj ? 49 : 25;
        for (int m = mstart; m < mend; m++) {
            const float4* cr = (const float4*)(cf32 + m * 16);
            float dot = 0.f;
            #pragma unroll
            for (int q = 0; q < 4; q++) {
                float4 w = cr[q];
                dot = __fmaf_rn(w.x, ffn[4*q+0], dot);
                dot = __fmaf_rn(w.y, ffn[4*q+1], dot);
                dot = __fmaf_rn(w.z, ffn[4*q+2], dot);
                dot = __fmaf_rn(w.w, ffn[4*q+3], dot);
            }
            float z = betaf + alphaf * dot;
            if (z > z1h) { z2h = z1h; z1h = z; bmh = m; }
            else if (z > z2h) { z2h = z; }
        }
        zb1[t] = z1h; zb2[t] = z2h; bmb[t] = bmh;
    }
    __syncthreads();

    // ---- merge halves (lower 256 threads own the decision) ----
    float z1 = 1e30f, z2 = 0.f;          // upper threads: gap huge -> no vote
    int bm = 0;
    float s = 0.f;
    if (t < 256) {
        float a1 = zb1[t],       a2 = zb2[t];       int abm = bmb[t];
        float b1 = zb1[t + 256], b2 = zb2[t + 256]; int bbm = bmb[t + 256];
        if (a1 >= b1) { z1 = a1; bm = abm; z2 = fmaxf(a2, b1); }
        else          { z1 = b1; bm = bbm; z2 = fmaxf(b2, a1); }
        s = 1.f / (1.f + expf(-z1));
    }

    // ---- per-CTA vote: exact fallback if any pixel too close to call ----
    if (__syncthreads_or((t < 256) && (z1 - z2) < 1e-4f)) {
        for (int i = t; i < 2048; i += NTHR) {
            int c = i >> 4, o = i & 15;
            fw2[i] = fw[o * CIN + c];
        }
        __syncthreads();

        unsigned long long fhi[8], flo[8];
        if (t < 256) {
            #pragma unroll
            for (int j = 0; j < 8; j++) { fhi[j] = pk2(OFFSET_F, OFFSET_F); flo[j] = 0ull; }
            const float* xf = x + (size_t)batch * COUT * HW
                                + (size_t)(gx * 16 + apr) * WIDTH + (gy * 16 + apc);
            #pragma unroll 4
            for (int c = 0; c < CIN; c++) {
                float x1 = __ldg(xf + (size_t)c * HW);
                unsigned long long x1d = pk2(x1, x1);
                const ulonglong2* wf = (const ulonglong2*)(fw2 + c * 16);
                #pragma unroll
                for (int j = 0; j < 4; j++) {
                    ulonglong2 a = wf[j];
                    dfacc2(fhi[2*j],   flo[2*j],   x1d, a.x);
                    dfacc2(fhi[2*j+1], flo[2*j+1], x1d, a.y);
                }
            }
        }
        __syncthreads();     // all fs readers done before fp64 overwrite
        if (t < 256) {
            #pragma unroll
            for (int j = 0; j < 8; j++) {
                float2 h = upk(fhi[j]), l = upk(flo[j]);
                fsd[(2*j)   * FSTR + t] =
                    ((double)__fadd_rn(h.x, -OFFSET_F) + (double)l.x) + (double)fbs[2*j];
                fsd[(2*j+1) * FSTR + t] =
                    ((double)__fadd_rn(h.y, -OFFSET_F) + (double)l.y) + (double)fbs[2*j+1];
            }
        }
        __syncthreads();

        for (int it = t; it < 784; it += NTHR) {
            int m = it >> 4, cc = it & 15;
            int i = m / 7, jj = m - i * 7;
            double ssum = 0.0;
            for (int r = SEG_S[i]; r < SEG_E[i]; r++)
                for (int q = SEG_S[jj]; q < SEG_E[jj]; q++)
                    ssum += fsd[cc * FSTR + r * 16 + q];
            cfd[it] = ssum * (double)SEG_I[i] * (double)SEG_I[jj];
        }
        __syncthreads();
        if (t < 49) {
            double ss = 0.0;
            #pragma unroll
            for (int cc = 0; cc < 16; cc++) { double v = cfd[t*16+cc]; ss = fma(v, v, ss); }
            double inv = 1.0 / fmax(sqrt(ss), 1e-12);
            #pragma unroll
            for (int cc = 0; cc < 16; cc++) cfd[t*16+cc] *= inv;
        }
        __syncthreads();

        if (t < 256) {
            double invf;
            {
                double ss = 0.0;
                #pragma unroll
                for (int cc = 0; cc < 16; cc++) {
                    double v = fsd[cc * FSTR + t];
                    ss = fma(v, v, ss);
                }
                invf = 1.0 / fmax(sqrt(ss), 1e-12);
            }
            const double alpha = (double)alphaf;
            const double beta  = (double)betaf;

            float mx32 = -1e30f;
            for (int m = 0; m < 49; m++) {
                const float4* cr = (const float4*)(cf32 + m * 16);
                float dot = 0.f;
                #pragma unroll
                for (int q = 0; q < 4; q++) {
                    float4 w = cr[q];
                    dot = __fmaf_rn(w.x, ffn[4*q+0], dot);
                    dot = __fmaf_rn(w.y, ffn[4*q+1], dot);
                    dot = __fmaf_rn(w.z, ffn[4*q+2], dot);
                    dot = __fmaf_rn(w.w, ffn[4*q+3], dot);
                }
                mx32 = fmaxf(mx32, dot);
            }
            const float thr = mx32 - 1e-4f;
            double dz1 = -1e300, dz2 = -1e300, dz3 = -1e300;
            int m1 = 0, m2 = 0, m3 = 0;
            for (int m = 0; m < 49; m++) {
                const float4* cr = (const float4*)(cf32 + m * 16);
                float dot = 0.f;
                #pragma unroll
                for (int q = 0; q < 4; q++) {
                    float4 w = cr[q];
                    dot = __fmaf_rn(w.x, ffn[4*q+0], dot);
                    dot = __fmaf_rn(w.y, ffn[4*q+1], dot);
                    dot = __fmaf_rn(w.z, ffn[4*q+2], dot);
                    dot = __fmaf_rn(w.w, ffn[4*q+3], dot);
                }
                if (dot >= thr) {
                    double dd = 0.0;
                    #pragma unroll
                    for (int cc = 0; cc < 16; cc++)
                        dd = fma(cfd[m*16+cc], fsd[cc * FSTR + t], dd);
                    double z = beta + alpha * (dd * invf);
                    if (z > dz1)      { dz3 = dz2; m3 = m2; dz2 = dz1; m2 = m1; dz1 = z; m1 = m; }
                    else if (z > dz2) { dz3 = dz2; m3 = m2; dz2 = z;  m2 = m; }
                    else if (z > dz3) { dz3 = z;  m3 = m; }
                }
            }
            float s1f = (float)(1.0 / (1.0 + exp(-dz1)));
            bm = m1;
            if (dz1 - dz2 < 1e-5) {
                float s2f = (float)(1.0 / (1.0 + exp(-dz2)));
                if (s2f == s1f && m2 < bm) bm = m2;
                if (dz1 - dz3 < 1e-5) {
                    float s3f = (float)(1.0 / (1.0 + exp(-dz3)));
                    if (s3f == s1f && m3 < bm) bm = m3;
                }
            }
            s = s1f;
        }
        __syncthreads();
    }

    // ---- share (s, bm) so both halves can split the atomic work ----
    if (t < 256) { zb1[t] = s; bmb[t] = bm; }
    __syncthreads();

    // ---- aggregate: lower does agd + cc 0-7, upper does cc 8-15 (reads vs) ----
    {
        float sv = zb1[px];
        int bmv = bmb[px];
        if (t < 256) atomicAdd(&agd[bmv], sv);
        const int cc0 = prj ? 8 : 0;
        #pragma unroll
        for (int cc = 0; cc < 8; cc++)
            atomicAdd(&agn[bmv * 16 + cc0 + cc], sv * vs[(cc0 + cc) * FSTR + px]);
    }
    __syncthreads();

    // ---- merge agg directly to global scratch; write (s, bm) ----
    for (int it = t; it < 784; it += NTHR) {
        int m = it >> 4;
        g_agg[(size_t)b * 784 + it] = (agn[it] + vc[it]) / (agd[m] + 1.f);
    }
    if (t < 256) {
        g_sv[b * 256 + t] = s;
        g_bm[b * 256 + t] = bm;
    }
}

// ---- Kernel 2: P = agg @ pw^T per block; y[o][n] = s_n * P[bm_n][o] + pb[o] ----
#define PSTR 261    // P row stride: 261 % 32 = 5, spreads cluster rows over banks
#define K2_OFF_P    0                            // float[49*261] = 51,156 B
#define K2_OFF_AGG  ((K2_OFF_P + 49*PSTR*4 + 15) & ~15)   // float[784], 16B-aligned
#define K2_OFF_SV   ((K2_OFF_AGG + 784*4 + 15) & ~15)     // float[256]
#define K2_OFF_BM   ((K2_OFF_SV + 256*4 + 15) & ~15)      // int[256]
#define K2_OFF_PBS  ((K2_OFF_BM + 256*4 + 15) & ~15)      // float[256]
#define SMEM2_BYTES (K2_OFF_PBS + 256*4)

extern "C" __global__ void __launch_bounds__(NTHR, 2)
lc_k2(const float* __restrict__ pw, const float* __restrict__ pbg,
      float* __restrict__ out)
{
    extern __shared__ char smraw[];
    float* Pm  = (float*)(smraw + K2_OFF_P);
    float* agg = (float*)(smraw + K2_OFF_AGG);
    float* sv  = (float*)(smraw + K2_OFF_SV);
    int*   bmv = (int*)(smraw + K2_OFF_BM);
    float* pbs = (float*)(smraw + K2_OFF_PBS);

    const int t = threadIdx.x;
    const int b = blockIdx.x;
    const int batch = b / 49;
    const int g = b - batch * 49;
    const int gx = g / 7, gy = g - (g / 7) * 7;

    for (int i = t; i < 784; i += NTHR) agg[i] = g_agg[(size_t)b * 784 + i];
    if (t < 256) {
        sv[t]  = g_sv[b * 256 + t];
        bmv[t] = g_bm[b * 256 + t];
        pbs[t] = pbg[t];
    }
    __syncthreads();

    // P-GEMM: thread = (o, m-half). pw row held in registers; agg broadcast LDS.
    {
        const int o = t & 255, mh = t >> 8;
        const float4* wrow = (const float4*)(pw + o * 16);
        float4 w0 = __ldg(wrow), w1 = __ldg(wrow + 1);
        float4 w2 = __ldg(wrow + 2), w3 = __ldg(wrow + 3);
        const int m0 = mh ? 25 : 0, m1 = mh ? 49 : 25;
        for (int m = m0; m < m1; m++) {
            const float4* ar = (const float4*)(agg + m * 16);
            float4 a0 = ar[0], a1 = ar[1], a2 = ar[2], a3 = ar[3];
            float dot = 0.f;
            dot = __fmaf_rn(w0.x, a0.x, dot); dot = __fmaf_rn(w0.y, a0.y, dot);
            dot = __fmaf_rn(w0.z, a0.z, dot); dot = __fmaf_rn(w0.w, a0.w, dot);
            dot = __fmaf_rn(w1.x, a1.x, dot); dot = __fmaf_rn(w1.y, a1.y, dot);
            dot = __fmaf_rn(w1.z, a1.z, dot); dot = __fmaf_rn(w1.w, a1.w, dot);
            dot = __fmaf_rn(w2.x, a2.x, dot); dot = __fmaf_rn(w2.y, a2.y, dot);
            dot = __fmaf_rn(w2.z, a2.z, dot); dot = __fmaf_rn(w2.w, a2.w, dot);
            dot = __fmaf_rn(w3.x, a3.x, dot); dot = __fmaf_rn(w3.y, a3.y, dot);
            dot = __fmaf_rn(w3.z, a3.z, dot); dot = __fmaf_rn(w3.w, a3.w, dot);
            Pm[m * PSTR + o] = dot;
        }
    }
    __syncthreads();

    // Epilogue: thread = (o-group of 64) x (pixel pair); coalesced STG.64
    {
        const int nid = t & 127, oid = t >> 7;
        const int n0 = 2 * nid;
        const float s0 = sv[n0], s1 = sv[n0 + 1];
        const float* P0 = Pm + bmv[n0] * PSTR;
        const float* P1 = Pm + bmv[n0 + 1] * PSTR;
        float* yb = out + (size_t)batch * COUT * HW
                        + (size_t)(gx * 16 + (n0 >> 4)) * WIDTH + (gy * 16 + (n0 & 15));
        const int obase = oid << 6;
        #pragma unroll 8
        for (int i = 0; i < 64; i++) {
            const int o = obase + i;
            float pbv = pbs[o];
            float2 r;
            r.x = __fmaf_rn(s0, P0[o], pbv);
            r.y = __fmaf_rn(s1, P1[o], pbv);
            *(float2*)(yb + (size_t)o * HW) = r;
        }
    }
}

extern "C" void kernel_launch(void* const* d_in, const int* in_sizes, int n_in,
                              void* d_out, int out_size) {
    const float* x   = (const float*)d_in[0];
    const float* fw  = (const float*)d_in[1];
    const float* fb  = (const float*)d_in[2];
    const float* vw  = (const float*)d_in[3];
    const float* vb  = (const float*)d_in[4];
    const float* pw  = (const float*)d_in[5];
    const float* pb  = (const float*)d_in[6];
    const float* sa  = (const float*)d_in[7];
    const float* sb  = (const float*)d_in[8];
    float* out = (float*)d_out;

    cudaFuncSetAttribute(lc_k1, cudaFuncAttributeMaxDynamicSharedMemorySize,
                         SMEM1_BYTES);
    cudaFuncSetAttribute(lc_k2, cudaFuncAttributeMaxDynamicSharedMemorySize,
                         SMEM2_BYTES);
    lc_k1<<<NBLK, NTHR, SMEM1_BYTES>>>(x, fw, fb, vw, vb, sa, sb);
    lc_k2<<<NBLK, NTHR, SMEM2_BYTES>>>(pw, pb, out);
}